// round 10
// baseline (speedup 1.0000x reference)
#include <cuda_runtime.h>
#include <cuda_bf16.h>
#include <cstdint>

#define B_   4
#define NQ   416
#define NC   257
#define D_   768
#define H_   6
#define DH   128
#define G_   104
#define R_   4
#define LORA 64
#define GL   (G_*LORA)   // 6656
#define EPS  1e-5f
#define SCALE_QK 0.08838834764831843f   // DH^-0.5

// ---------------- scratch (device globals: allocation-free) ----------------
__device__ __align__(16) float g_q[B_*NQ*D_];
__device__ __align__(16) float g_k[B_*NC*D_];
__device__ __align__(16) float g_mid[B_*NC*GL];      // RAW (pre-LN) mid
__device__ __align__(16) float g_attn[B_*H_*NQ*NC];
__device__ __align__(16) float g_Mg[G_*LORA*LORA];
__device__ __align__(16) float g_wbar[G_*LORA];
__device__ __align__(16) float g_lnmu[B_*NC];        // mid-LN row stats
__device__ __align__(16) float g_lnrs[B_*NC];

// bf16 hi/lo operands
__device__ __align__(16) __nv_bfloat16 s_xh[B_*NQ*D_],  s_xl[B_*NQ*D_];
__device__ __align__(16) __nv_bfloat16 s_ch[B_*NC*D_],  s_cl[B_*NC*D_];
__device__ __align__(16) __nv_bfloat16 s_oph[B_*NQ*D_], s_opl[B_*NQ*D_];
__device__ __align__(16) __nv_bfloat16 s_wqh[D_*D_],  s_wql[D_*D_];
__device__ __align__(16) __nv_bfloat16 s_wkh[D_*D_],  s_wkl[D_*D_];
__device__ __align__(16) __nv_bfloat16 s_woh[D_*D_],  s_wol[D_*D_];
__device__ __align__(16) __nv_bfloat16 s_wvh[(size_t)D_*GL], s_wvl[(size_t)D_*GL];

// ---------------- helpers ---------------------------------------------------
__device__ __forceinline__ uint32_t smem_u32(const void* p) {
    uint32_t a;
    asm("{ .reg .u64 t; cvta.to.shared.u64 t, %1; cvt.u32.u64 %0, t; }" : "=r"(a) : "l"(p));
    return a;
}
__device__ __forceinline__ void ldsm_x4(uint32_t& r0, uint32_t& r1,
                                        uint32_t& r2, uint32_t& r3, uint32_t addr) {
    asm volatile("ldmatrix.sync.aligned.m8n8.x4.shared.b16 {%0,%1,%2,%3}, [%4];"
                 : "=r"(r0), "=r"(r1), "=r"(r2), "=r"(r3) : "r"(addr));
}
__device__ __forceinline__ void mma16816(float* d, const uint32_t* a,
                                         uint32_t b0, uint32_t b1) {
    asm volatile("mma.sync.aligned.m16n8k16.row.col.f32.bf16.bf16.f32 "
                 "{%0,%1,%2,%3}, {%4,%5,%6,%7}, {%8,%9}, {%0,%1,%2,%3};"
                 : "+f"(d[0]), "+f"(d[1]), "+f"(d[2]), "+f"(d[3])
                 : "r"(a[0]), "r"(a[1]), "r"(a[2]), "r"(a[3]), "r"(b0), "r"(b1));
}
#define CP16(dst, src) asm volatile("cp.async.ca.shared.global [%0], [%1], 16;" :: "r"(dst), "l"(src))
#define CP_COMMIT()    asm volatile("cp.async.commit_group;" ::: "memory")
#define CP_WAIT1()     asm volatile("cp.async.wait_group 1;" ::: "memory")
#define CP_WAIT0()     asm volatile("cp.async.wait_group 0;" ::: "memory")

// ---------------- split kernels (fp32 -> bf16 hi/lo) ------------------------
__global__ void split_kernel(const float* __restrict__ X,
                             __nv_bfloat16* __restrict__ hi,
                             __nv_bfloat16* __restrict__ lo, int n4) {
    int i = blockIdx.x * 256 + threadIdx.x;
    if (i >= n4) return;
    float4 v = reinterpret_cast<const float4*>(X)[i];
    __nv_bfloat16 h0 = __float2bfloat16_rn(v.x), h1 = __float2bfloat16_rn(v.y);
    __nv_bfloat16 h2 = __float2bfloat16_rn(v.z), h3 = __float2bfloat16_rn(v.w);
    reinterpret_cast<__nv_bfloat162*>(hi)[i*2]   = __halves2bfloat162(h0, h1);
    reinterpret_cast<__nv_bfloat162*>(hi)[i*2+1] = __halves2bfloat162(h2, h3);
    reinterpret_cast<__nv_bfloat162*>(lo)[i*2]   =
        __halves2bfloat162(__float2bfloat16_rn(v.x - __bfloat162float(h0)),
                           __float2bfloat16_rn(v.y - __bfloat162float(h1)));
    reinterpret_cast<__nv_bfloat162*>(lo)[i*2+1] =
        __halves2bfloat162(__float2bfloat16_rn(v.z - __bfloat162float(h2)),
                           __float2bfloat16_rn(v.w - __bfloat162float(h3)));
}

// W[k][n] fp32 -> WtHi/Lo[n][k] bf16: 64k x 32n tiles, 16B coalesced stores
__global__ void splitT_kernel(const float* __restrict__ W,
                              __nv_bfloat16* __restrict__ hiT,
                              __nv_bfloat16* __restrict__ loT, int K, int N) {
    __shared__ float t[64][33];
    const int nb = blockIdx.x * 32, kb = blockIdx.y * 64;
    const int tid = threadIdx.x;
    for (int i = tid; i < 2048; i += 256) {
        int ky = i >> 5, nx = i & 31;
        t[ky][nx] = W[(size_t)(kb + ky) * N + nb + nx];
    }
    __syncthreads();
    const int ny = tid >> 3, k8 = (tid & 7) * 8;
    __align__(16) __nv_bfloat16 hv[8], lv[8];
#pragma unroll
    for (int j = 0; j < 8; j++) {
        float v = t[k8 + j][ny];
        hv[j] = __float2bfloat16_rn(v);
        lv[j] = __float2bfloat16_rn(v - __bfloat162float(hv[j]));
    }
    size_t o = (size_t)(nb + ny) * K + kb + k8;
    *reinterpret_cast<uint4*>(hiT + o) = *reinterpret_cast<const uint4*>(hv);
    *reinterpret_cast<uint4*>(loT + o) = *reinterpret_cast<const uint4*>(lv);
}

// ---------------- pipelined 3xBF16 HMMA GEMM, 64x64 tile, 256 threads ------
#define AST   72
#define OF_AH 0
#define OF_AL 9216
#define OF_BH 18432
#define OF_BL 27648
#define BUFSZ 36864
#define HG_SMEM (2*BUFSZ)    // 73728 -> 3 CTAs/SM, 24 warps/SM

__global__ void __launch_bounds__(256) hmma_gemm(const __nv_bfloat16* __restrict__ Ah,
                                                 const __nv_bfloat16* __restrict__ Al,
                                                 const __nv_bfloat16* __restrict__ Bh,
                                                 const __nv_bfloat16* __restrict__ Bl,
                                                 float* __restrict__ C,
                                                 int M, int N, int K) {
    extern __shared__ __align__(128) char smem[];
    const uint32_t sb = smem_u32(smem);
    const int tid = threadIdx.x, lane = tid & 31, warp = tid >> 5;
    const int warp_m = warp & 1, warp_n = warp >> 1;    // 2 x 4, warp tile 32x16
    const int row0 = blockIdx.y * 64, n0 = blockIdx.x * 64;

    float acc[2][2][4];
#pragma unroll
    for (int mi = 0; mi < 2; mi++)
#pragma unroll
        for (int nt = 0; nt < 2; nt++)
#pragma unroll
            for (int r = 0; r < 4; r++) acc[mi][nt][r] = 0.f;

    uint32_t aAddr[2];
#pragma unroll
    for (int mi = 0; mi < 2; mi++)
        aAddr[mi] = sb + OF_AH
                  + (uint32_t)((warp_m*32 + mi*16 + (lane & 15)) * (AST*2))
                  + (uint32_t)((lane >> 4) * 16);
    uint32_t bAddr = sb + OF_BH
                   + (uint32_t)((warp_n*16 + (lane & 15)) * (AST*2))
                   + (uint32_t)((lane >> 4) * 16);

    const int NCH = K >> 6;

    auto stage = [&](int kc, int bi) {
        const int k0 = kc << 6;
        const uint32_t bb = sb + bi * BUFSZ;
#pragma unroll
        for (int t = 0; t < 2; t++) {
            int idx = t * 256 + tid;             // 512: A rows x segs
            int r = idx >> 3, seg = idx & 7;
            int ra = row0 + r; if (ra >= M) ra = M - 1;
            size_t so = (size_t)ra * K + k0 + seg * 8;
            uint32_t dof = (uint32_t)(r * (AST*2) + seg * 16);
            CP16(bb + OF_AH + dof, Ah + so);
            CP16(bb + OF_AL + dof, Al + so);
        }
#pragma unroll
        for (int t = 0; t < 2; t++) {
            int idx = t * 256 + tid;             // 512: B rows x segs
            int r = idx >> 3, seg = idx & 7;
            size_t so = (size_t)(n0 + r) * K + k0 + seg * 8;
            uint32_t dof = (uint32_t)(r * (AST*2) + seg * 16);
            CP16(bb + OF_BH + dof, Bh + so);
            CP16(bb + OF_BL + dof, Bl + so);
        }
        CP_COMMIT();
    };

    stage(0, 0);
    for (int kc = 0; kc < NCH; kc++) {
        __syncthreads();
        if (kc + 1 < NCH) { stage(kc + 1, (kc + 1) & 1); CP_WAIT1(); }
        else CP_WAIT0();
        __syncthreads();
        const uint32_t bb = (uint32_t)((kc & 1) * BUFSZ);
#pragma unroll
        for (int ks = 0; ks < 4; ks++) {
            const uint32_t kb = bb + (uint32_t)(ks * 32);
            uint32_t ah[2][4], al[2][4], bh[4], bl[4];
#pragma unroll
            for (int mi = 0; mi < 2; mi++) {
                ldsm_x4(ah[mi][0], ah[mi][1], ah[mi][2], ah[mi][3], aAddr[mi] + kb);
                ldsm_x4(al[mi][0], al[mi][1], al[mi][2], al[mi][3], aAddr[mi] + kb + (OF_AL - OF_AH));
            }
            ldsm_x4(bh[0], bh[1], bh[2], bh[3], bAddr + kb);
            ldsm_x4(bl[0], bl[1], bl[2], bl[3], bAddr + kb + (OF_BL - OF_BH));
#pragma unroll
            for (int mi = 0; mi < 2; mi++)
#pragma unroll
                for (int nt = 0; nt < 2; nt++) {
                    mma16816(acc[mi][nt], ah[mi], bh[nt], bh[nt+2]);
                    mma16816(acc[mi][nt], ah[mi], bl[nt], bl[nt+2]);
                    mma16816(acc[mi][nt], al[mi], bh[nt], bh[nt+2]);
                }
        }
    }

#pragma unroll
    for (int mi = 0; mi < 2; mi++) {
        int rA = row0 + warp_m*32 + mi*16 + (lane >> 2);
#pragma unroll
        for (int nt = 0; nt < 2; nt++) {
            int col = n0 + warp_n*16 + nt*8 + (lane & 3)*2;
            if (rA < M)
                *reinterpret_cast<float2*>(C + (size_t)rA*N + col)
                    = make_float2(acc[mi][nt][0], acc[mi][nt][1]);
            if (rA + 8 < M)
                *reinterpret_cast<float2*>(C + (size_t)(rA + 8)*N + col)
                    = make_float2(acc[mi][nt][2], acc[mi][nt][3]);
        }
    }
}

// ---------------- one-pass row LayerNorm (float4, N<=768) -------------------
__global__ void ln_rows(const float* __restrict__ X, const float* __restrict__ g,
                        const float* __restrict__ b, float* __restrict__ Y, int N) {
    extern __shared__ float row[];
    __shared__ float red[256], red2[256];
    const int r = blockIdx.x, tid = threadIdx.x;
    const float4* x4 = reinterpret_cast<const float4*>(X + (size_t)r * N);
    float4* row4 = reinterpret_cast<float4*>(row);
    const int n4 = N >> 2;
    float s = 0.f, s2 = 0.f;
    for (int j = tid; j < n4; j += 256) {
        float4 v = x4[j];
        row4[j] = v;
        s  += v.x + v.y + v.z + v.w;
        s2 += v.x*v.x + v.y*v.y + v.z*v.z + v.w*v.w;
    }
    red[tid] = s; red2[tid] = s2; __syncthreads();
    for (int o = 128; o; o >>= 1) {
        if (tid < o) { red[tid] += red[tid+o]; red2[tid] += red2[tid+o]; }
        __syncthreads();
    }
    float mean = red[0] / (float)N;
    float rstd = rsqrtf(red2[0] / (float)N - mean*mean + EPS);
    const float4* g4 = reinterpret_cast<const float4*>(g);
    const float4* b4 = reinterpret_cast<const float4*>(b);
    float4* y4 = reinterpret_cast<float4*>(Y + (size_t)r * N);
    for (int j = tid; j < n4; j += 256) {
        float4 v = row4[j], gg = g4[j], bb = b4[j];
        v.x = (v.x - mean)*rstd*gg.x + bb.x;
        v.y = (v.y - mean)*rstd*gg.y + bb.y;
        v.z = (v.z - mean)*rstd*gg.z + bb.z;
        v.w = (v.w - mean)*rstd*gg.w + bb.w;
        y4[j] = v;
    }
}

// ---------------- mid-LN row statistics (no write-back of normalized mid) --
__global__ void mid_stats_kernel(const float* __restrict__ X) {
    __shared__ float red[256], red2[256];
    const int r = blockIdx.x, tid = threadIdx.x;
    const float4* x4 = reinterpret_cast<const float4*>(X + (size_t)r * GL);
    float s = 0.f, s2 = 0.f;
    for (int j = tid; j < GL/4; j += 256) {
        float4 v = x4[j];
        s  += v.x + v.y + v.z + v.w;
        s2 += v.x*v.x + v.y*v.y + v.z*v.z + v.w*v.w;
    }
    red[tid] = s; red2[tid] = s2; __syncthreads();
    for (int o = 128; o; o >>= 1) {
        if (tid < o) { red[tid] += red[tid+o]; red2[tid] += red2[tid+o]; }
        __syncthreads();
    }
    if (tid == 0) {
        float mean = red[0] / (float)GL;
        g_lnmu[r] = mean;
        g_lnrs[r] = rsqrtf(red2[0] / (float)GL - mean*mean + EPS);
    }
}

// ---------------- per-group Gram matrix + mean weight ----------------------
__global__ void prep_kernel(const float* __restrict__ Wconv) {
    __shared__ float s_w[64*65];
    const int g = blockIdx.x, tid = threadIdx.x;
    const int i = tid >> 2, j0 = (tid & 3) * 16;
    float acc[16];
#pragma unroll
    for (int p = 0; p < 16; p++) acc[p] = 0.f;
    float wsum = 0.f;
    for (int dt = 0; dt < 12; dt++) {
        __syncthreads();
        for (int idx = tid; idx < 4096; idx += 256) {
            int l = idx >> 6, c = idx & 63;
            s_w[l*65 + c] = Wconv[((size_t)(g*64 + l))*D_ + dt*64 + c];
        }
        __syncthreads();
        for (int c = 0; c < 64; c++) {
            float wi = s_w[i*65 + c];
#pragma unroll
            for (int p = 0; p < 16; p++) acc[p] += wi * s_w[(j0+p)*65 + c];
        }
        if (tid < 64)
            for (int c = 0; c < 64; c++) wsum += s_w[tid*65 + c];
    }
#pragma unroll
    for (int p = 0; p < 16; p++)
        g_Mg[(size_t)g*4096 + i*64 + j0 + p] = acc[p];
    if (tid < 64) g_wbar[g*64 + tid] = wsum * (1.0f / (float)D_);
}

// ---------------- fused sim + softmax --------------------------------------
__global__ void sim_softmax_kernel() {
    extern __shared__ float sm[];
    float* sq = sm;              // 32*129
    float* sk = sq + 32*129;     // 32*129
    float* ss = sk + 32*129;     // 32*257
    const int bh = blockIdx.y, b = bh / H_, h = bh - b*H_;
    const int i0 = blockIdx.x * 32;
    const int tid = threadIdx.x;

    for (int idx = tid; idx < 32*128; idx += 256) {
        int li = idx >> 7, d = idx & 127;
        sq[li*129 + d] = g_q[((size_t)(b*NQ + i0 + li))*D_ + h*DH + d];
    }
    const int li = tid >> 3, jq = tid & 7;
    for (int jt = 0; jt < 9; jt++) {
        int jb = jt * 32;
        __syncthreads();
        for (int idx = tid; idx < 32*128; idx += 256) {
            int lj = idx >> 7, d = idx & 127;
            int j = jb + lj;
            sk[lj*129 + d] = (j < NC) ? g_k[((size_t)(b*NC + j))*D_ + h*DH + d] : 0.f;
        }
        __syncthreads();
        const float* qrow = &sq[li*129];
        const float* k0 = &sk[(jq*4+0)*129];
        const float* k1 = &sk[(jq*4+1)*129];
        const float* k2 = &sk[(jq*4+2)*129];
        const float* k3 = &sk[(jq*4+3)*129];
        float a0=0.f, a1=0.f, a2=0.f, a3=0.f;
#pragma unroll 8
        for (int d = 0; d < 128; d++) {
            float qv = qrow[d];
            a0 += qv*k0[d]; a1 += qv*k1[d]; a2 += qv*k2[d]; a3 += qv*k3[d];
        }
        int jbb = jb + jq*4;
        if (jbb + 0 < NC) ss[li*NC + jbb + 0] = a0 * SCALE_QK;
        if (jbb + 1 < NC) ss[li*NC + jbb + 1] = a1 * SCALE_QK;
        if (jbb + 2 < NC) ss[li*NC + jbb + 2] = a2 * SCALE_QK;
        if (jbb + 3 < NC) ss[li*NC + jbb + 3] = a3 * SCALE_QK;
    }
    __syncthreads();
    const int warp = tid >> 5, lane = tid & 31;
    for (int rrow = warp; rrow < 32; rrow += 8) {
        float* r = &ss[rrow*NC];
        float mx = -1e30f;
        for (int j = lane; j < NC; j += 32) mx = fmaxf(mx, r[j]);
        for (int o = 16; o; o >>= 1) mx = fmaxf(mx, __shfl_xor_sync(0xffffffffu, mx, o));
        float sum = 0.f;
        for (int j = lane; j < NC; j += 32) { float e = __expf(r[j] - mx); r[j] = e; sum += e; }
        for (int o = 16; o; o >>= 1) sum += __shfl_xor_sync(0xffffffffu, sum, o);
        float inv = 1.f / sum;
        float* out = &g_attn[((size_t)(bh*NQ + i0 + rrow))*NC];
        for (int j = lane; j < NC; j += 32) out[j] = r[j] * inv;
    }
}

// ---------------- fused conv+LN+skip+attention-contract (512 threads) ------
// Applies mid-LN inline (raw mid + row stats + gv1/bv1 affine).
#define SFT 512
__global__ void __launch_bounds__(SFT) stageF_kernel(const float* __restrict__ ctx,
                              const float* __restrict__ Wconv,
                              const float* __restrict__ gv2,
                              const float* __restrict__ bv2,
                              const float* __restrict__ gv1,
                              const float* __restrict__ bv1,
                              __nv_bfloat16* __restrict__ oph,
                              __nv_bfloat16* __restrict__ opl) {
    extern __shared__ float sm[];
    float* s_mid = sm;                   // 257*65
    float* s_M   = s_mid + 257*65;       // 4096
    float* s_wb  = s_M   + 4096;         // 64
    float* s_mu  = s_wb  + 64;           // 257
    float* s_rs  = s_mu  + 257;          // 257
    float* s_a   = s_rs  + 257;          // 24*257
    float* s_c   = s_a   + 24*257;       // 24*64
    float* s_s1  = s_c   + 24*64;        // 24
    float* s_s0  = s_s1  + 24;           // 24
    float* s_ctx = s_s0  + 24;           // 257*33
    float* s_W   = s_ctx + 257*33;       // 64*33
    float* s_red = s_W   + 64*33;        // 16*4*32
    float* s_lmu = s_red + 2048;         // 257
    float* s_lrs = s_lmu + 257;          // 257

    const int g = blockIdx.x, b = blockIdx.y;
    const int tid = threadIdx.x;

    for (int n = tid; n < NC; n += SFT) {
        s_lmu[n] = g_lnmu[b*NC + n];
        s_lrs[n] = g_lnrs[b*NC + n];
    }
    __syncthreads();

    // inline LN of mid while loading: l = tid&63 is loop-invariant
    {
        const float gvl = gv1[g*64 + (tid & 63)];
        const float bvl = bv1[g*64 + (tid & 63)];
        for (int i = tid; i < NC*LORA; i += SFT) {
            int n = i >> 6, l = i & 63;
            float raw = g_mid[((size_t)(b*NC + n))*GL + g*LORA + l];
            s_mid[n*65 + l] = (raw - s_lmu[n]) * s_lrs[n] * gvl + bvl;
        }
    }
    for (int i = tid; i < 4096; i += SFT) s_M[i] = g_Mg[(size_t)g*4096 + i];
    if (tid < 64) s_wb[tid] = g_wbar[g*64 + tid];
    for (int i = tid; i < 24*NC; i += SFT) {
        int hr = i / NC, n = i - hr*NC;
        int h = hr >> 2, r = hr & 3;
        s_a[hr*NC + n] = g_attn[((size_t)((b*H_ + h)*NQ + (r*G_ + g)))*NC + n];
    }
    __syncthreads();

    {
        const int half = tid & 1;
        const int l0 = half * 32;
#pragma unroll
        for (int nb = 0; nb < 2; nb++) {
            int n = (tid >> 1) + nb * 256;
            float mu = 0.f, qf = 0.f;
            if (n < NC) {
                const float* m = &s_mid[n*65];
#pragma unroll 8
                for (int l = l0; l < l0 + 32; l++) mu += m[l]*s_wb[l];
                for (int i2 = l0; i2 < l0 + 32; i2++) {
                    const float* Mi = &s_M[i2*64];
                    float t = 0.f;
#pragma unroll 16
                    for (int j = 0; j < 64; j++) t += Mi[j]*m[j];
                    qf += m[i2]*t;
                }
            }
            mu += __shfl_xor_sync(0xffffffffu, mu, 1);
            qf += __shfl_xor_sync(0xffffffffu, qf, 1);
            if (n < NC && half == 0) {
                float var = qf * (1.0f/(float)D_) - mu*mu;
                s_mu[n] = mu;
                s_rs[n] = rsqrtf(var + EPS);
            }
        }
    }
    __syncthreads();

    for (int idx = tid; idx < 24*66; idx += SFT) {
        int hr = idx / 66, j = idx - hr*66;
        const float* a = &s_a[hr*NC];
        float acc = 0.f;
        if (j < 64) {
            for (int n = 0; n < NC; n++) acc += a[n]*s_rs[n]*s_mid[n*65 + j];
            s_c[hr*64 + j] = acc;
        } else if (j == 64) {
            for (int n = 0; n < NC; n++) acc += a[n]*s_rs[n]*s_mu[n];
            s_s1[hr] = acc;
        } else {
            for (int n = 0; n < NC; n++) acc += a[n];
            s_s0[hr] = acc;
        }
    }
    __syncthreads();

    const int dc = tid & 31, seg = tid >> 5;   // 16 segments
    for (int h = 0; h < H_; h++) {
        for (int dt = 0; dt < 4; dt++) {
            int dbase = h*DH + dt*32;
            __syncthreads();
            for (int i = tid; i < NC*32; i += SFT) {
                int n = i >> 5, c = i & 31;
                s_ctx[n*33 + c] = ctx[((size_t)(b*NC + n))*D_ + dbase + c];
            }
            for (int i = tid; i < 64*32; i += SFT) {
                int l = i >> 5, c = i & 31;
                s_W[l*33 + c] = Wconv[((size_t)(g*64 + l))*D_ + dbase + c];
            }
            __syncthreads();
            float a0=0.f, a1=0.f, a2=0.f, a3=0.f;
            for (int n = seg; n < NC; n += 16) {
                float cv = s_ctx[n*33 + dc];
                a0 += s_a[(h*4+0)*NC + n]*cv;
                a1 += s_a[(h*4+1)*NC + n]*cv;
                a2 += s_a[(h*4+2)*NC + n]*cv;
                a3 += s_a[(h*4+3)*NC + n]*cv;
            }
            s_red[(seg*4+0)*32 + dc] = a0;
            s_red[(seg*4+1)*32 + dc] = a1;
            s_red[(seg*4+2)*32 + dc] = a2;
            s_red[(seg*4+3)*32 + dc] = a3;
            __syncthreads();
            if (tid < 128) {
                const int r = tid >> 5;
                int dglob = dbase + dc;
                float gvd = gv2[dglob], bvd = bv2[dglob];
                float cs = 0.f;
#pragma unroll
                for (int s = 0; s < 16; s++) cs += s_red[(s*4+r)*32 + dc];
                int hr = h*4 + r;
                const float* c = &s_c[hr*64];
                float wd = 0.f;
#pragma unroll 16
                for (int l = 0; l < 64; l++) wd += c[l]*s_W[l*33 + dc];
                float o = gvd*(wd - s_s1[hr]) + bvd*s_s0[hr] + cs;
                size_t oidx = ((size_t)(b*NQ + r*G_ + g))*D_ + dglob;
                __nv_bfloat16 hv = __float2bfloat16_rn(o);
                oph[oidx] = hv;
                opl[oidx] = __float2bfloat16_rn(o - __bfloat162float(hv));
            }
        }
    }
}

// ---------------- launch ----------------------------------------------------
extern "C" void kernel_launch(void* const* d_in, const int* in_sizes, int n_in,
                              void* d_out, int out_size) {
    const float* x     = (const float*)d_in[0];
    const float* ctx   = (const float*)d_in[1];
    const float* Wq    = (const float*)d_in[2];
    const float* gq    = (const float*)d_in[3];
    const float* bq    = (const float*)d_in[4];
    const float* Wk    = (const float*)d_in[5];
    const float* gk    = (const float*)d_in[6];
    const float* bk    = (const float*)d_in[7];
    const float* Wv    = (const float*)d_in[8];
    const float* gv1   = (const float*)d_in[9];
    const float* bv1   = (const float*)d_in[10];
    const float* Wconv = (const float*)d_in[11];
    const float* gv2   = (const float*)d_in[12];
    const float* bv2   = (const float*)d_in[13];
    const float* Wo    = (const float*)d_in[14];
    const float* go    = (const float*)d_in[15];
    const float* bo    = (const float*)d_in[16];
    float* out = (float*)d_out;

    float *pq, *pk, *pmid;
    cudaGetSymbolAddress((void**)&pq, g_q);
    cudaGetSymbolAddress((void**)&pk, g_k);
    cudaGetSymbolAddress((void**)&pmid, g_mid);
    __nv_bfloat16 *xh,*xl,*ch,*cl,*oph,*opl,*wqh,*wql,*wkh,*wkl,*woh,*wol,*wvh,*wvl;
    cudaGetSymbolAddress((void**)&xh,  s_xh);  cudaGetSymbolAddress((void**)&xl,  s_xl);
    cudaGetSymbolAddress((void**)&ch,  s_ch);  cudaGetSymbolAddress((void**)&cl,  s_cl);
    cudaGetSymbolAddress((void**)&oph, s_oph); cudaGetSymbolAddress((void**)&opl, s_opl);
    cudaGetSymbolAddress((void**)&wqh, s_wqh); cudaGetSymbolAddress((void**)&wql, s_wql);
    cudaGetSymbolAddress((void**)&wkh, s_wkh); cudaGetSymbolAddress((void**)&wkl, s_wkl);
    cudaGetSymbolAddress((void**)&woh, s_woh); cudaGetSymbolAddress((void**)&wol, s_wol);
    cudaGetSymbolAddress((void**)&wvh, s_wvh); cudaGetSymbolAddress((void**)&wvl, s_wvl);

    const int SIM_SMEM = (32*129*2 + 32*257) * 4;
    const int SF_SMEM  = (257*65 + 4096 + 64 + 257 + 257 + 24*257
                          + 24*64 + 48 + 257*33 + 64*33 + 2048 + 514) * 4;
    cudaFuncSetAttribute(sim_softmax_kernel,
                         cudaFuncAttributeMaxDynamicSharedMemorySize, SIM_SMEM);
    cudaFuncSetAttribute(stageF_kernel,
                         cudaFuncAttributeMaxDynamicSharedMemorySize, SF_SMEM);
    cudaFuncSetAttribute(hmma_gemm,
                         cudaFuncAttributeMaxDynamicSharedMemorySize, HG_SMEM);

    // 0 split ctx, 1 splitT Wv, 2 split x, 3 mid GEMM (profiled)
    split_kernel<<<(B_*NC*D_/4 + 255)/256, 256>>>(ctx, ch, cl, B_*NC*D_/4);
    splitT_kernel<<<dim3(GL/32, D_/64), 256>>>(Wv, wvh, wvl, D_, GL);
    split_kernel<<<(B_*NQ*D_/4 + 255)/256, 256>>>(x, xh, xl, B_*NQ*D_/4);
    hmma_gemm<<<dim3(GL/64, 17), 256, HG_SMEM>>>(ch, cl, wvh, wvl, pmid, B_*NC, GL, D_);
    mid_stats_kernel<<<B_*NC, 256>>>(pmid);
    // q / k
    splitT_kernel<<<dim3(D_/32, D_/64), 256>>>(Wq, wqh, wql, D_, D_);
    hmma_gemm<<<dim3(D_/64, 26), 256, HG_SMEM>>>(xh, xl, wqh, wql, pq, B_*NQ, D_, D_);
    ln_rows<<<B_*NQ, 256, D_*4>>>(pq, gq, bq, pq, D_);
    splitT_kernel<<<dim3(D_/32, D_/64), 256>>>(Wk, wkh, wkl, D_, D_);
    hmma_gemm<<<dim3(D_/64, 17), 256, HG_SMEM>>>(ch, cl, wkh, wkl, pk, B_*NC, D_, D_);
    ln_rows<<<B_*NC, 256, D_*4>>>(pk, gk, bk, pk, D_);
    // rest
    splitT_kernel<<<dim3(D_/32, D_/64), 256>>>(Wo, woh, wol, D_, D_);
    prep_kernel<<<G_, 256>>>(Wconv);
    sim_softmax_kernel<<<dim3(NQ/32, B_*H_), 256, SIM_SMEM>>>();
    stageF_kernel<<<dim3(G_, B_), SFT, SF_SMEM>>>(ctx, Wconv, gv2, bv2, gv1, bv1, oph, opl);
    hmma_gemm<<<dim3(D_/64, 26), 256, HG_SMEM>>>(oph, opl, woh, wol, pq, B_*NQ, D_, D_);
    ln_rows<<<B_*NQ, 256, D_*4>>>(pq, go, bo, out, D_);
}

// round 11
// speedup vs baseline: 1.0033x; 1.0033x over previous
#include <cuda_runtime.h>
#include <cuda_bf16.h>
#include <cstdint>

#define B_   4
#define NQ   416
#define NC   257
#define D_   768
#define H_   6
#define DH   128
#define G_   104
#define R_   4
#define LORA 64
#define GL   (G_*LORA)   // 6656
#define EPS  1e-5f
#define SCALE_QK 0.08838834764831843f   // DH^-0.5

// ---------------- scratch (device globals: allocation-free) ----------------
__device__ __align__(16) float g_q[B_*NQ*D_];
__device__ __align__(16) float g_k[B_*NC*D_];
__device__ __align__(16) float g_mid[B_*NC*GL];      // RAW (pre-LN) mid
__device__ __align__(16) float g_attn[B_*H_*NQ*NC];
__device__ __align__(16) float g_Mg[G_*LORA*LORA];
__device__ __align__(16) float g_wbar[G_*LORA];
__device__ __align__(16) float g_lnmu[B_*NC];        // mid-LN row stats
__device__ __align__(16) float g_lnrs[B_*NC];

// bf16 hi/lo operands
__device__ __align__(16) __nv_bfloat16 s_xh[B_*NQ*D_],  s_xl[B_*NQ*D_];
__device__ __align__(16) __nv_bfloat16 s_ch[B_*NC*D_],  s_cl[B_*NC*D_];
__device__ __align__(16) __nv_bfloat16 s_oph[B_*NQ*D_], s_opl[B_*NQ*D_];
__device__ __align__(16) __nv_bfloat16 s_wqh[D_*D_],  s_wql[D_*D_];
__device__ __align__(16) __nv_bfloat16 s_wkh[D_*D_],  s_wkl[D_*D_];
__device__ __align__(16) __nv_bfloat16 s_woh[D_*D_],  s_wol[D_*D_];
__device__ __align__(16) __nv_bfloat16 s_wvh[(size_t)D_*GL], s_wvl[(size_t)D_*GL];

// ---------------- helpers ---------------------------------------------------
__device__ __forceinline__ uint32_t smem_u32(const void* p) {
    uint32_t a;
    asm("{ .reg .u64 t; cvta.to.shared.u64 t, %1; cvt.u32.u64 %0, t; }" : "=r"(a) : "l"(p));
    return a;
}
__device__ __forceinline__ void ldsm_x4(uint32_t& r0, uint32_t& r1,
                                        uint32_t& r2, uint32_t& r3, uint32_t addr) {
    asm volatile("ldmatrix.sync.aligned.m8n8.x4.shared.b16 {%0,%1,%2,%3}, [%4];"
                 : "=r"(r0), "=r"(r1), "=r"(r2), "=r"(r3) : "r"(addr));
}
__device__ __forceinline__ void mma16816(float* d, const uint32_t* a,
                                         uint32_t b0, uint32_t b1) {
    asm volatile("mma.sync.aligned.m16n8k16.row.col.f32.bf16.bf16.f32 "
                 "{%0,%1,%2,%3}, {%4,%5,%6,%7}, {%8,%9}, {%0,%1,%2,%3};"
                 : "+f"(d[0]), "+f"(d[1]), "+f"(d[2]), "+f"(d[3])
                 : "r"(a[0]), "r"(a[1]), "r"(a[2]), "r"(a[3]), "r"(b0), "r"(b1));
}
#define CP16(dst, src) asm volatile("cp.async.ca.shared.global [%0], [%1], 16;" :: "r"(dst), "l"(src))
#define CP_COMMIT()    asm volatile("cp.async.commit_group;" ::: "memory")
#define CP_WAIT1()     asm volatile("cp.async.wait_group 1;" ::: "memory")
#define CP_WAIT0()     asm volatile("cp.async.wait_group 0;" ::: "memory")

// ---------------- split kernels (fp32 -> bf16 hi/lo) ------------------------
__global__ void split_kernel(const float* __restrict__ X,
                             __nv_bfloat16* __restrict__ hi,
                             __nv_bfloat16* __restrict__ lo, int n4) {
    int i = blockIdx.x * 256 + threadIdx.x;
    if (i >= n4) return;
    float4 v = reinterpret_cast<const float4*>(X)[i];
    __nv_bfloat16 h0 = __float2bfloat16_rn(v.x), h1 = __float2bfloat16_rn(v.y);
    __nv_bfloat16 h2 = __float2bfloat16_rn(v.z), h3 = __float2bfloat16_rn(v.w);
    reinterpret_cast<__nv_bfloat162*>(hi)[i*2]   = __halves2bfloat162(h0, h1);
    reinterpret_cast<__nv_bfloat162*>(hi)[i*2+1] = __halves2bfloat162(h2, h3);
    reinterpret_cast<__nv_bfloat162*>(lo)[i*2]   =
        __halves2bfloat162(__float2bfloat16_rn(v.x - __bfloat162float(h0)),
                           __float2bfloat16_rn(v.y - __bfloat162float(h1)));
    reinterpret_cast<__nv_bfloat162*>(lo)[i*2+1] =
        __halves2bfloat162(__float2bfloat16_rn(v.z - __bfloat162float(h2)),
                           __float2bfloat16_rn(v.w - __bfloat162float(h3)));
}

// W[k][n] fp32 -> WtHi/Lo[n][k] bf16: 64k x 32n tiles, 16B coalesced stores
__global__ void splitT_kernel(const float* __restrict__ W,
                              __nv_bfloat16* __restrict__ hiT,
                              __nv_bfloat16* __restrict__ loT, int K, int N) {
    __shared__ float t[64][33];
    const int nb = blockIdx.x * 32, kb = blockIdx.y * 64;
    const int tid = threadIdx.x;
    for (int i = tid; i < 2048; i += 256) {
        int ky = i >> 5, nx = i & 31;
        t[ky][nx] = W[(size_t)(kb + ky) * N + nb + nx];
    }
    __syncthreads();
    const int ny = tid >> 3, k8 = (tid & 7) * 8;
    __align__(16) __nv_bfloat16 hv[8], lv[8];
#pragma unroll
    for (int j = 0; j < 8; j++) {
        float v = t[k8 + j][ny];
        hv[j] = __float2bfloat16_rn(v);
        lv[j] = __float2bfloat16_rn(v - __bfloat162float(hv[j]));
    }
    size_t o = (size_t)(nb + ny) * K + kb + k8;
    *reinterpret_cast<uint4*>(hiT + o) = *reinterpret_cast<const uint4*>(hv);
    *reinterpret_cast<uint4*>(loT + o) = *reinterpret_cast<const uint4*>(lv);
}

// ---------------- pipelined 3xBF16 HMMA GEMM, 64x64 tile, 256 threads ------
#define AST   72
#define OF_AH 0
#define OF_AL 9216
#define OF_BH 18432
#define OF_BL 27648
#define BUFSZ 36864
#define HG_SMEM (2*BUFSZ)    // 73728 -> 3 CTAs/SM, 24 warps/SM

__global__ void __launch_bounds__(256) hmma_gemm(const __nv_bfloat16* __restrict__ Ah,
                                                 const __nv_bfloat16* __restrict__ Al,
                                                 const __nv_bfloat16* __restrict__ Bh,
                                                 const __nv_bfloat16* __restrict__ Bl,
                                                 float* __restrict__ C,
                                                 int M, int N, int K) {
    extern __shared__ __align__(128) char smem[];
    const uint32_t sb = smem_u32(smem);
    const int tid = threadIdx.x, lane = tid & 31, warp = tid >> 5;
    const int warp_m = warp & 1, warp_n = warp >> 1;    // 2 x 4, warp tile 32x16
    const int row0 = blockIdx.y * 64, n0 = blockIdx.x * 64;

    float acc[2][2][4];
#pragma unroll
    for (int mi = 0; mi < 2; mi++)
#pragma unroll
        for (int nt = 0; nt < 2; nt++)
#pragma unroll
            for (int r = 0; r < 4; r++) acc[mi][nt][r] = 0.f;

    uint32_t aAddr[2];
#pragma unroll
    for (int mi = 0; mi < 2; mi++)
        aAddr[mi] = sb + OF_AH
                  + (uint32_t)((warp_m*32 + mi*16 + (lane & 15)) * (AST*2))
                  + (uint32_t)((lane >> 4) * 16);
    uint32_t bAddr = sb + OF_BH
                   + (uint32_t)((warp_n*16 + (lane & 15)) * (AST*2))
                   + (uint32_t)((lane >> 4) * 16);

    const int NCH = K >> 6;

    auto stage = [&](int kc, int bi) {
        const int k0 = kc << 6;
        const uint32_t bb = sb + bi * BUFSZ;
#pragma unroll
        for (int t = 0; t < 2; t++) {
            int idx = t * 256 + tid;             // 512: A rows x segs
            int r = idx >> 3, seg = idx & 7;
            int ra = row0 + r; if (ra >= M) ra = M - 1;
            size_t so = (size_t)ra * K + k0 + seg * 8;
            uint32_t dof = (uint32_t)(r * (AST*2) + seg * 16);
            CP16(bb + OF_AH + dof, Ah + so);
            CP16(bb + OF_AL + dof, Al + so);
        }
#pragma unroll
        for (int t = 0; t < 2; t++) {
            int idx = t * 256 + tid;             // 512: B rows x segs
            int r = idx >> 3, seg = idx & 7;
            size_t so = (size_t)(n0 + r) * K + k0 + seg * 8;
            uint32_t dof = (uint32_t)(r * (AST*2) + seg * 16);
            CP16(bb + OF_BH + dof, Bh + so);
            CP16(bb + OF_BL + dof, Bl + so);
        }
        CP_COMMIT();
    };

    stage(0, 0);
    for (int kc = 0; kc < NCH; kc++) {
        __syncthreads();
        if (kc + 1 < NCH) { stage(kc + 1, (kc + 1) & 1); CP_WAIT1(); }
        else CP_WAIT0();
        __syncthreads();
        const uint32_t bb = (uint32_t)((kc & 1) * BUFSZ);
#pragma unroll
        for (int ks = 0; ks < 4; ks++) {
            const uint32_t kb = bb + (uint32_t)(ks * 32);
            uint32_t ah[2][4], al[2][4], bh[4], bl[4];
#pragma unroll
            for (int mi = 0; mi < 2; mi++) {
                ldsm_x4(ah[mi][0], ah[mi][1], ah[mi][2], ah[mi][3], aAddr[mi] + kb);
                ldsm_x4(al[mi][0], al[mi][1], al[mi][2], al[mi][3], aAddr[mi] + kb + (OF_AL - OF_AH));
            }
            ldsm_x4(bh[0], bh[1], bh[2], bh[3], bAddr + kb);
            ldsm_x4(bl[0], bl[1], bl[2], bl[3], bAddr + kb + (OF_BL - OF_BH));
#pragma unroll
            for (int mi = 0; mi < 2; mi++)
#pragma unroll
                for (int nt = 0; nt < 2; nt++) {
                    mma16816(acc[mi][nt], ah[mi], bh[nt], bh[nt+2]);
                    mma16816(acc[mi][nt], ah[mi], bl[nt], bl[nt+2]);
                    mma16816(acc[mi][nt], al[mi], bh[nt], bh[nt+2]);
                }
        }
    }

#pragma unroll
    for (int mi = 0; mi < 2; mi++) {
        int rA = row0 + warp_m*32 + mi*16 + (lane >> 2);
#pragma unroll
        for (int nt = 0; nt < 2; nt++) {
            int col = n0 + warp_n*16 + nt*8 + (lane & 3)*2;
            if (rA < M)
                *reinterpret_cast<float2*>(C + (size_t)rA*N + col)
                    = make_float2(acc[mi][nt][0], acc[mi][nt][1]);
            if (rA + 8 < M)
                *reinterpret_cast<float2*>(C + (size_t)(rA + 8)*N + col)
                    = make_float2(acc[mi][nt][2], acc[mi][nt][3]);
        }
    }
}

// ---------------- one-pass row LayerNorm (float4, N<=768) -------------------
__global__ void ln_rows(const float* __restrict__ X, const float* __restrict__ g,
                        const float* __restrict__ b, float* __restrict__ Y, int N) {
    extern __shared__ float row[];
    __shared__ float red[256], red2[256];
    const int r = blockIdx.x, tid = threadIdx.x;
    const float4* x4 = reinterpret_cast<const float4*>(X + (size_t)r * N);
    float4* row4 = reinterpret_cast<float4*>(row);
    const int n4 = N >> 2;
    float s = 0.f, s2 = 0.f;
    for (int j = tid; j < n4; j += 256) {
        float4 v = x4[j];
        row4[j] = v;
        s  += v.x + v.y + v.z + v.w;
        s2 += v.x*v.x + v.y*v.y + v.z*v.z + v.w*v.w;
    }
    red[tid] = s; red2[tid] = s2; __syncthreads();
    for (int o = 128; o; o >>= 1) {
        if (tid < o) { red[tid] += red[tid+o]; red2[tid] += red2[tid+o]; }
        __syncthreads();
    }
    float mean = red[0] / (float)N;
    float rstd = rsqrtf(red2[0] / (float)N - mean*mean + EPS);
    const float4* g4 = reinterpret_cast<const float4*>(g);
    const float4* b4 = reinterpret_cast<const float4*>(b);
    float4* y4 = reinterpret_cast<float4*>(Y + (size_t)r * N);
    for (int j = tid; j < n4; j += 256) {
        float4 v = row4[j], gg = g4[j], bb = b4[j];
        v.x = (v.x - mean)*rstd*gg.x + bb.x;
        v.y = (v.y - mean)*rstd*gg.y + bb.y;
        v.z = (v.z - mean)*rstd*gg.z + bb.z;
        v.w = (v.w - mean)*rstd*gg.w + bb.w;
        y4[j] = v;
    }
}

// ---------------- mid-LN row statistics (no write-back of normalized mid) --
__global__ void mid_stats_kernel(const float* __restrict__ X) {
    __shared__ float red[256], red2[256];
    const int r = blockIdx.x, tid = threadIdx.x;
    const float4* x4 = reinterpret_cast<const float4*>(X + (size_t)r * GL);
    float s = 0.f, s2 = 0.f;
    for (int j = tid; j < GL/4; j += 256) {
        float4 v = x4[j];
        s  += v.x + v.y + v.z + v.w;
        s2 += v.x*v.x + v.y*v.y + v.z*v.z + v.w*v.w;
    }
    red[tid] = s; red2[tid] = s2; __syncthreads();
    for (int o = 128; o; o >>= 1) {
        if (tid < o) { red[tid] += red[tid+o]; red2[tid] += red2[tid+o]; }
        __syncthreads();
    }
    if (tid == 0) {
        float mean = red[0] / (float)GL;
        g_lnmu[r] = mean;
        g_lnrs[r] = rsqrtf(red2[0] / (float)GL - mean*mean + EPS);
    }
}

// ---------------- per-group Gram matrix + mean weight ----------------------
__global__ void prep_kernel(const float* __restrict__ Wconv) {
    __shared__ float s_w[64*65];
    const int g = blockIdx.x, tid = threadIdx.x;
    const int i = tid >> 2, j0 = (tid & 3) * 16;
    float acc[16];
#pragma unroll
    for (int p = 0; p < 16; p++) acc[p] = 0.f;
    float wsum = 0.f;
    for (int dt = 0; dt < 12; dt++) {
        __syncthreads();
        for (int idx = tid; idx < 4096; idx += 256) {
            int l = idx >> 6, c = idx & 63;
            s_w[l*65 + c] = Wconv[((size_t)(g*64 + l))*D_ + dt*64 + c];
        }
        __syncthreads();
        for (int c = 0; c < 64; c++) {
            float wi = s_w[i*65 + c];
#pragma unroll
            for (int p = 0; p < 16; p++) acc[p] += wi * s_w[(j0+p)*65 + c];
        }
        if (tid < 64)
            for (int c = 0; c < 64; c++) wsum += s_w[tid*65 + c];
    }
#pragma unroll
    for (int p = 0; p < 16; p++)
        g_Mg[(size_t)g*4096 + i*64 + j0 + p] = acc[p];
    if (tid < 64) g_wbar[g*64 + tid] = wsum * (1.0f / (float)D_);
}

// ---------------- fused sim + softmax --------------------------------------
__global__ void sim_softmax_kernel() {
    extern __shared__ float sm[];
    float* sq = sm;              // 32*129
    float* sk = sq + 32*129;     // 32*129
    float* ss = sk + 32*129;     // 32*257
    const int bh = blockIdx.y, b = bh / H_, h = bh - b*H_;
    const int i0 = blockIdx.x * 32;
    const int tid = threadIdx.x;

    for (int idx = tid; idx < 32*128; idx += 256) {
        int li = idx >> 7, d = idx & 127;
        sq[li*129 + d] = g_q[((size_t)(b*NQ + i0 + li))*D_ + h*DH + d];
    }
    const int li = tid >> 3, jq = tid & 7;
    for (int jt = 0; jt < 9; jt++) {
        int jb = jt * 32;
        __syncthreads();
        for (int idx = tid; idx < 32*128; idx += 256) {
            int lj = idx >> 7, d = idx & 127;
            int j = jb + lj;
            sk[lj*129 + d] = (j < NC) ? g_k[((size_t)(b*NC + j))*D_ + h*DH + d] : 0.f;
        }
        __syncthreads();
        const float* qrow = &sq[li*129];
        const float* k0 = &sk[(jq*4+0)*129];
        const float* k1 = &sk[(jq*4+1)*129];
        const float* k2 = &sk[(jq*4+2)*129];
        const float* k3 = &sk[(jq*4+3)*129];
        float a0=0.f, a1=0.f, a2=0.f, a3=0.f;
#pragma unroll 8
        for (int d = 0; d < 128; d++) {
            float qv = qrow[d];
            a0 += qv*k0[d]; a1 += qv*k1[d]; a2 += qv*k2[d]; a3 += qv*k3[d];
        }
        int jbb = jb + jq*4;
        if (jbb + 0 < NC) ss[li*NC + jbb + 0] = a0 * SCALE_QK;
        if (jbb + 1 < NC) ss[li*NC + jbb + 1] = a1 * SCALE_QK;
        if (jbb + 2 < NC) ss[li*NC + jbb + 2] = a2 * SCALE_QK;
        if (jbb + 3 < NC) ss[li*NC + jbb + 3] = a3 * SCALE_QK;
    }
    __syncthreads();
    const int warp = tid >> 5, lane = tid & 31;
    for (int rrow = warp; rrow < 32; rrow += 8) {
        float* r = &ss[rrow*NC];
        float mx = -1e30f;
        for (int j = lane; j < NC; j += 32) mx = fmaxf(mx, r[j]);
        for (int o = 16; o; o >>= 1) mx = fmaxf(mx, __shfl_xor_sync(0xffffffffu, mx, o));
        float sum = 0.f;
        for (int j = lane; j < NC; j += 32) { float e = __expf(r[j] - mx); r[j] = e; sum += e; }
        for (int o = 16; o; o >>= 1) sum += __shfl_xor_sync(0xffffffffu, sum, o);
        float inv = 1.f / sum;
        float* out = &g_attn[((size_t)(bh*NQ + i0 + rrow))*NC];
        for (int j = lane; j < NC; j += 32) out[j] = r[j] * inv;
    }
}

// ---------------- fused conv+LN+skip+attention-contract (512 threads) ------
// Applies mid-LN inline (raw mid + row stats + gv1/bv1 affine).
#define SFT 512
__global__ void __launch_bounds__(SFT) stageF_kernel(const float* __restrict__ ctx,
                              const float* __restrict__ Wconv,
                              const float* __restrict__ gv2,
                              const float* __restrict__ bv2,
                              const float* __restrict__ gv1,
                              const float* __restrict__ bv1,
                              __nv_bfloat16* __restrict__ oph,
                              __nv_bfloat16* __restrict__ opl) {
    extern __shared__ float sm[];
    float* s_mid = sm;                   // 257*65
    float* s_M   = s_mid + 257*65;       // 4096
    float* s_wb  = s_M   + 4096;         // 64
    float* s_mu  = s_wb  + 64;           // 257
    float* s_rs  = s_mu  + 257;          // 257
    float* s_a   = s_rs  + 257;          // 24*257
    float* s_c   = s_a   + 24*257;       // 24*64
    float* s_s1  = s_c   + 24*64;        // 24
    float* s_s0  = s_s1  + 24;           // 24
    float* s_ctx = s_s0  + 24;           // 257*33
    float* s_W   = s_ctx + 257*33;       // 64*33
    float* s_red = s_W   + 64*33;        // 16*4*32
    float* s_lmu = s_red + 2048;         // 257
    float* s_lrs = s_lmu + 257;          // 257

    const int g = blockIdx.x, b = blockIdx.y;
    const int tid = threadIdx.x;

    for (int n = tid; n < NC; n += SFT) {
        s_lmu[n] = g_lnmu[b*NC + n];
        s_lrs[n] = g_lnrs[b*NC + n];
    }
    __syncthreads();

    // inline LN of mid while loading: l = tid&63 is loop-invariant
    {
        const float gvl = gv1[g*64 + (tid & 63)];
        const float bvl = bv1[g*64 + (tid & 63)];
        for (int i = tid; i < NC*LORA; i += SFT) {
            int n = i >> 6, l = i & 63;
            float raw = g_mid[((size_t)(b*NC + n))*GL + g*LORA + l];
            s_mid[n*65 + l] = (raw - s_lmu[n]) * s_lrs[n] * gvl + bvl;
        }
    }
    for (int i = tid; i < 4096; i += SFT) s_M[i] = g_Mg[(size_t)g*4096 + i];
    if (tid < 64) s_wb[tid] = g_wbar[g*64 + tid];
    for (int i = tid; i < 24*NC; i += SFT) {
        int hr = i / NC, n = i - hr*NC;
        int h = hr >> 2, r = hr & 3;
        s_a[hr*NC + n] = g_attn[((size_t)((b*H_ + h)*NQ + (r*G_ + g)))*NC + n];
    }
    __syncthreads();

    {
        const int half = tid & 1;
        const int l0 = half * 32;
#pragma unroll
        for (int nb = 0; nb < 2; nb++) {
            int n = (tid >> 1) + nb * 256;
            float mu = 0.f, qf = 0.f;
            if (n < NC) {
                const float* m = &s_mid[n*65];
#pragma unroll 8
                for (int l = l0; l < l0 + 32; l++) mu += m[l]*s_wb[l];
                for (int i2 = l0; i2 < l0 + 32; i2++) {
                    const float* Mi = &s_M[i2*64];
                    float t = 0.f;
#pragma unroll 16
                    for (int j = 0; j < 64; j++) t += Mi[j]*m[j];
                    qf += m[i2]*t;
                }
            }
            mu += __shfl_xor_sync(0xffffffffu, mu, 1);
            qf += __shfl_xor_sync(0xffffffffu, qf, 1);
            if (n < NC && half == 0) {
                float var = qf * (1.0f/(float)D_) - mu*mu;
                s_mu[n] = mu;
                s_rs[n] = rsqrtf(var + EPS);
            }
        }
    }
    __syncthreads();

    for (int idx = tid; idx < 24*66; idx += SFT) {
        int hr = idx / 66, j = idx - hr*66;
        const float* a = &s_a[hr*NC];
        float acc = 0.f;
        if (j < 64) {
            for (int n = 0; n < NC; n++) acc += a[n]*s_rs[n]*s_mid[n*65 + j];
            s_c[hr*64 + j] = acc;
        } else if (j == 64) {
            for (int n = 0; n < NC; n++) acc += a[n]*s_rs[n]*s_mu[n];
            s_s1[hr] = acc;
        } else {
            for (int n = 0; n < NC; n++) acc += a[n];
            s_s0[hr] = acc;
        }
    }
    __syncthreads();

    const int dc = tid & 31, seg = tid >> 5;   // 16 segments
    for (int h = 0; h < H_; h++) {
        for (int dt = 0; dt < 4; dt++) {
            int dbase = h*DH + dt*32;
            __syncthreads();
            for (int i = tid; i < NC*32; i += SFT) {
                int n = i >> 5, c = i & 31;
                s_ctx[n*33 + c] = ctx[((size_t)(b*NC + n))*D_ + dbase + c];
            }
            for (int i = tid; i < 64*32; i += SFT) {
                int l = i >> 5, c = i & 31;
                s_W[l*33 + c] = Wconv[((size_t)(g*64 + l))*D_ + dbase + c];
            }
            __syncthreads();
            float a0=0.f, a1=0.f, a2=0.f, a3=0.f;
            for (int n = seg; n < NC; n += 16) {
                float cv = s_ctx[n*33 + dc];
                a0 += s_a[(h*4+0)*NC + n]*cv;
                a1 += s_a[(h*4+1)*NC + n]*cv;
                a2 += s_a[(h*4+2)*NC + n]*cv;
                a3 += s_a[(h*4+3)*NC + n]*cv;
            }
            s_red[(seg*4+0)*32 + dc] = a0;
            s_red[(seg*4+1)*32 + dc] = a1;
            s_red[(seg*4+2)*32 + dc] = a2;
            s_red[(seg*4+3)*32 + dc] = a3;
            __syncthreads();
            if (tid < 128) {
                const int r = tid >> 5;
                int dglob = dbase + dc;
                float gvd = gv2[dglob], bvd = bv2[dglob];
                float cs = 0.f;
#pragma unroll
                for (int s = 0; s < 16; s++) cs += s_red[(s*4+r)*32 + dc];
                int hr = h*4 + r;
                const float* c = &s_c[hr*64];
                float wd = 0.f;
#pragma unroll 16
                for (int l = 0; l < 64; l++) wd += c[l]*s_W[l*33 + dc];
                float o = gvd*(wd - s_s1[hr]) + bvd*s_s0[hr] + cs;
                size_t oidx = ((size_t)(b*NQ + r*G_ + g))*D_ + dglob;
                __nv_bfloat16 hv = __float2bfloat16_rn(o);
                oph[oidx] = hv;
                opl[oidx] = __float2bfloat16_rn(o - __bfloat162float(hv));
            }
        }
    }
}

// ---------------- launch ----------------------------------------------------
extern "C" void kernel_launch(void* const* d_in, const int* in_sizes, int n_in,
                              void* d_out, int out_size) {
    const float* x     = (const float*)d_in[0];
    const float* ctx   = (const float*)d_in[1];
    const float* Wq    = (const float*)d_in[2];
    const float* gq    = (const float*)d_in[3];
    const float* bq    = (const float*)d_in[4];
    const float* Wk    = (const float*)d_in[5];
    const float* gk    = (const float*)d_in[6];
    const float* bk    = (const float*)d_in[7];
    const float* Wv    = (const float*)d_in[8];
    const float* gv1   = (const float*)d_in[9];
    const float* bv1   = (const float*)d_in[10];
    const float* Wconv = (const float*)d_in[11];
    const float* gv2   = (const float*)d_in[12];
    const float* bv2   = (const float*)d_in[13];
    const float* Wo    = (const float*)d_in[14];
    const float* go    = (const float*)d_in[15];
    const float* bo    = (const float*)d_in[16];
    float* out = (float*)d_out;

    float *pq, *pk, *pmid;
    cudaGetSymbolAddress((void**)&pq, g_q);
    cudaGetSymbolAddress((void**)&pk, g_k);
    cudaGetSymbolAddress((void**)&pmid, g_mid);
    __nv_bfloat16 *xh,*xl,*ch,*cl,*oph,*opl,*wqh,*wql,*wkh,*wkl,*woh,*wol,*wvh,*wvl;
    cudaGetSymbolAddress((void**)&xh,  s_xh);  cudaGetSymbolAddress((void**)&xl,  s_xl);
    cudaGetSymbolAddress((void**)&ch,  s_ch);  cudaGetSymbolAddress((void**)&cl,  s_cl);
    cudaGetSymbolAddress((void**)&oph, s_oph); cudaGetSymbolAddress((void**)&opl, s_opl);
    cudaGetSymbolAddress((void**)&wqh, s_wqh); cudaGetSymbolAddress((void**)&wql, s_wql);
    cudaGetSymbolAddress((void**)&wkh, s_wkh); cudaGetSymbolAddress((void**)&wkl, s_wkl);
    cudaGetSymbolAddress((void**)&woh, s_woh); cudaGetSymbolAddress((void**)&wol, s_wol);
    cudaGetSymbolAddress((void**)&wvh, s_wvh); cudaGetSymbolAddress((void**)&wvl, s_wvl);

    const int SIM_SMEM = (32*129*2 + 32*257) * 4;
    const int SF_SMEM  = (257*65 + 4096 + 64 + 257 + 257 + 24*257
                          + 24*64 + 48 + 257*33 + 64*33 + 2048 + 514) * 4;
    cudaFuncSetAttribute(sim_softmax_kernel,
                         cudaFuncAttributeMaxDynamicSharedMemorySize, SIM_SMEM);
    cudaFuncSetAttribute(stageF_kernel,
                         cudaFuncAttributeMaxDynamicSharedMemorySize, SF_SMEM);
    cudaFuncSetAttribute(hmma_gemm,
                         cudaFuncAttributeMaxDynamicSharedMemorySize, HG_SMEM);

    // 0 split ctx, 1 splitT Wv, 2 split x, 3 mid GEMM (profiled)
    split_kernel<<<(B_*NC*D_/4 + 255)/256, 256>>>(ctx, ch, cl, B_*NC*D_/4);
    splitT_kernel<<<dim3(GL/32, D_/64), 256>>>(Wv, wvh, wvl, D_, GL);
    split_kernel<<<(B_*NQ*D_/4 + 255)/256, 256>>>(x, xh, xl, B_*NQ*D_/4);
    hmma_gemm<<<dim3(GL/64, 17), 256, HG_SMEM>>>(ch, cl, wvh, wvl, pmid, B_*NC, GL, D_);
    mid_stats_kernel<<<B_*NC, 256>>>(pmid);
    // q / k
    splitT_kernel<<<dim3(D_/32, D_/64), 256>>>(Wq, wqh, wql, D_, D_);
    hmma_gemm<<<dim3(D_/64, 26), 256, HG_SMEM>>>(xh, xl, wqh, wql, pq, B_*NQ, D_, D_);
    ln_rows<<<B_*NQ, 256, D_*4>>>(pq, gq, bq, pq, D_);
    splitT_kernel<<<dim3(D_/32, D_/64), 256>>>(Wk, wkh, wkl, D_, D_);
    hmma_gemm<<<dim3(D_/64, 17), 256, HG_SMEM>>>(ch, cl, wkh, wkl, pk, B_*NC, D_, D_);
    ln_rows<<<B_*NC, 256, D_*4>>>(pk, gk, bk, pk, D_);
    // rest
    splitT_kernel<<<dim3(D_/32, D_/64), 256>>>(Wo, woh, wol, D_, D_);
    prep_kernel<<<G_, 256>>>(Wconv);
    sim_softmax_kernel<<<dim3(NQ/32, B_*H_), 256, SIM_SMEM>>>();
    stageF_kernel<<<dim3(G_, B_), SFT, SF_SMEM>>>(ctx, Wconv, gv2, bv2, gv1, bv1, oph, opl);
    hmma_gemm<<<dim3(D_/64, 26), 256, HG_SMEM>>>(oph, opl, woh, wol, pq, B_*NQ, D_, D_);
    ln_rows<<<B_*NQ, 256, D_*4>>>(pq, go, bo, out, D_);
}

// round 12
// speedup vs baseline: 1.0037x; 1.0005x over previous
#include <cuda_runtime.h>
#include <cuda_bf16.h>
#include <cstdint>

#define B_   4
#define NQ   416
#define NC   257
#define D_   768
#define H_   6
#define DH   128
#define G_   104
#define R_   4
#define LORA 64
#define GL   (G_*LORA)   // 6656
#define EPS  1e-5f
#define SCALE_QK 0.08838834764831843f   // DH^-0.5

// ---------------- scratch (device globals: allocation-free) ----------------
__device__ __align__(16) float g_q[B_*NQ*D_];
__device__ __align__(16) float g_k[B_*NC*D_];
__device__ __align__(16) float g_mid[B_*NC*GL];      // RAW (pre-LN) mid
__device__ __align__(16) float g_attn[B_*H_*NQ*NC];
__device__ __align__(16) float g_Mg[G_*LORA*LORA];
__device__ __align__(16) float g_wbar[G_*LORA];
__device__ __align__(16) float g_lnmu[B_*NC];        // mid-LN row stats
__device__ __align__(16) float g_lnrs[B_*NC];

// bf16 hi/lo operands
__device__ __align__(16) __nv_bfloat16 s_xh[B_*NQ*D_],  s_xl[B_*NQ*D_];
__device__ __align__(16) __nv_bfloat16 s_ch[B_*NC*D_],  s_cl[B_*NC*D_];
__device__ __align__(16) __nv_bfloat16 s_oph[B_*NQ*D_], s_opl[B_*NQ*D_];
__device__ __align__(16) __nv_bfloat16 s_wqh[D_*D_],  s_wql[D_*D_];
__device__ __align__(16) __nv_bfloat16 s_wkh[D_*D_],  s_wkl[D_*D_];
__device__ __align__(16) __nv_bfloat16 s_woh[D_*D_],  s_wol[D_*D_];
__device__ __align__(16) __nv_bfloat16 s_wvh[(size_t)D_*GL], s_wvl[(size_t)D_*GL];

// ---------------- helpers ---------------------------------------------------
__device__ __forceinline__ uint32_t smem_u32(const void* p) {
    uint32_t a;
    asm("{ .reg .u64 t; cvta.to.shared.u64 t, %1; cvt.u32.u64 %0, t; }" : "=r"(a) : "l"(p));
    return a;
}
__device__ __forceinline__ void ldsm_x4(uint32_t& r0, uint32_t& r1,
                                        uint32_t& r2, uint32_t& r3, uint32_t addr) {
    asm volatile("ldmatrix.sync.aligned.m8n8.x4.shared.b16 {%0,%1,%2,%3}, [%4];"
                 : "=r"(r0), "=r"(r1), "=r"(r2), "=r"(r3) : "r"(addr));
}
__device__ __forceinline__ void mma16816(float* d, const uint32_t* a,
                                         uint32_t b0, uint32_t b1) {
    asm volatile("mma.sync.aligned.m16n8k16.row.col.f32.bf16.bf16.f32 "
                 "{%0,%1,%2,%3}, {%4,%5,%6,%7}, {%8,%9}, {%0,%1,%2,%3};"
                 : "+f"(d[0]), "+f"(d[1]), "+f"(d[2]), "+f"(d[3])
                 : "r"(a[0]), "r"(a[1]), "r"(a[2]), "r"(a[3]), "r"(b0), "r"(b1));
}
#define CP16(dst, src) asm volatile("cp.async.ca.shared.global [%0], [%1], 16;" :: "r"(dst), "l"(src))
#define CP_COMMIT()    asm volatile("cp.async.commit_group;" ::: "memory")
#define CP_WAIT1()     asm volatile("cp.async.wait_group 1;" ::: "memory")
#define CP_WAIT0()     asm volatile("cp.async.wait_group 0;" ::: "memory")

// ---------------- split kernels (fp32 -> bf16 hi/lo) ------------------------
__global__ void split_kernel(const float* __restrict__ X,
                             __nv_bfloat16* __restrict__ hi,
                             __nv_bfloat16* __restrict__ lo, int n4) {
    int i = blockIdx.x * 256 + threadIdx.x;
    if (i >= n4) return;
    float4 v = reinterpret_cast<const float4*>(X)[i];
    __nv_bfloat16 h0 = __float2bfloat16_rn(v.x), h1 = __float2bfloat16_rn(v.y);
    __nv_bfloat16 h2 = __float2bfloat16_rn(v.z), h3 = __float2bfloat16_rn(v.w);
    reinterpret_cast<__nv_bfloat162*>(hi)[i*2]   = __halves2bfloat162(h0, h1);
    reinterpret_cast<__nv_bfloat162*>(hi)[i*2+1] = __halves2bfloat162(h2, h3);
    reinterpret_cast<__nv_bfloat162*>(lo)[i*2]   =
        __halves2bfloat162(__float2bfloat16_rn(v.x - __bfloat162float(h0)),
                           __float2bfloat16_rn(v.y - __bfloat162float(h1)));
    reinterpret_cast<__nv_bfloat162*>(lo)[i*2+1] =
        __halves2bfloat162(__float2bfloat16_rn(v.z - __bfloat162float(h2)),
                           __float2bfloat16_rn(v.w - __bfloat162float(h3)));
}

// W[k][n] fp32 -> WtHi/Lo[n][k] bf16: 64k x 32n tiles, 16B coalesced stores
__global__ void splitT_kernel(const float* __restrict__ W,
                              __nv_bfloat16* __restrict__ hiT,
                              __nv_bfloat16* __restrict__ loT, int K, int N) {
    __shared__ float t[64][33];
    const int nb = blockIdx.x * 32, kb = blockIdx.y * 64;
    const int tid = threadIdx.x;
    for (int i = tid; i < 2048; i += 256) {
        int ky = i >> 5, nx = i & 31;
        t[ky][nx] = W[(size_t)(kb + ky) * N + nb + nx];
    }
    __syncthreads();
    const int ny = tid >> 3, k8 = (tid & 7) * 8;
    __align__(16) __nv_bfloat16 hv[8], lv[8];
#pragma unroll
    for (int j = 0; j < 8; j++) {
        float v = t[k8 + j][ny];
        hv[j] = __float2bfloat16_rn(v);
        lv[j] = __float2bfloat16_rn(v - __bfloat162float(hv[j]));
    }
    size_t o = (size_t)(nb + ny) * K + kb + k8;
    *reinterpret_cast<uint4*>(hiT + o) = *reinterpret_cast<const uint4*>(hv);
    *reinterpret_cast<uint4*>(loT + o) = *reinterpret_cast<const uint4*>(lv);
}

// ---------------- pipelined 3xBF16 HMMA GEMM, 64x64 tile, 256 threads ------
#define AST   72
#define OF_AH 0
#define OF_AL 9216
#define OF_BH 18432
#define OF_BL 27648
#define BUFSZ 36864
#define HG_SMEM (2*BUFSZ)    // 73728 -> 3 CTAs/SM, 24 warps/SM

__global__ void __launch_bounds__(256) hmma_gemm(const __nv_bfloat16* __restrict__ Ah,
                                                 const __nv_bfloat16* __restrict__ Al,
                                                 const __nv_bfloat16* __restrict__ Bh,
                                                 const __nv_bfloat16* __restrict__ Bl,
                                                 float* __restrict__ C,
                                                 int M, int N, int K) {
    extern __shared__ __align__(128) char smem[];
    const uint32_t sb = smem_u32(smem);
    const int tid = threadIdx.x, lane = tid & 31, warp = tid >> 5;
    const int warp_m = warp & 1, warp_n = warp >> 1;    // 2 x 4, warp tile 32x16
    const int row0 = blockIdx.y * 64, n0 = blockIdx.x * 64;

    float acc[2][2][4];
#pragma unroll
    for (int mi = 0; mi < 2; mi++)
#pragma unroll
        for (int nt = 0; nt < 2; nt++)
#pragma unroll
            for (int r = 0; r < 4; r++) acc[mi][nt][r] = 0.f;

    uint32_t aAddr[2];
#pragma unroll
    for (int mi = 0; mi < 2; mi++)
        aAddr[mi] = sb + OF_AH
                  + (uint32_t)((warp_m*32 + mi*16 + (lane & 15)) * (AST*2))
                  + (uint32_t)((lane >> 4) * 16);
    uint32_t bAddr = sb + OF_BH
                   + (uint32_t)((warp_n*16 + (lane & 15)) * (AST*2))
                   + (uint32_t)((lane >> 4) * 16);

    const int NCH = K >> 6;

    auto stage = [&](int kc, int bi) {
        const int k0 = kc << 6;
        const uint32_t bb = sb + bi * BUFSZ;
#pragma unroll
        for (int t = 0; t < 2; t++) {
            int idx = t * 256 + tid;             // 512: A rows x segs
            int r = idx >> 3, seg = idx & 7;
            int ra = row0 + r; if (ra >= M) ra = M - 1;
            size_t so = (size_t)ra * K + k0 + seg * 8;
            uint32_t dof = (uint32_t)(r * (AST*2) + seg * 16);
            CP16(bb + OF_AH + dof, Ah + so);
            CP16(bb + OF_AL + dof, Al + so);
        }
#pragma unroll
        for (int t = 0; t < 2; t++) {
            int idx = t * 256 + tid;             // 512: B rows x segs
            int r = idx >> 3, seg = idx & 7;
            size_t so = (size_t)(n0 + r) * K + k0 + seg * 8;
            uint32_t dof = (uint32_t)(r * (AST*2) + seg * 16);
            CP16(bb + OF_BH + dof, Bh + so);
            CP16(bb + OF_BL + dof, Bl + so);
        }
        CP_COMMIT();
    };

    stage(0, 0);
    for (int kc = 0; kc < NCH; kc++) {
        __syncthreads();
        if (kc + 1 < NCH) { stage(kc + 1, (kc + 1) & 1); CP_WAIT1(); }
        else CP_WAIT0();
        __syncthreads();
        const uint32_t bb = (uint32_t)((kc & 1) * BUFSZ);
#pragma unroll
        for (int ks = 0; ks < 4; ks++) {
            const uint32_t kb = bb + (uint32_t)(ks * 32);
            uint32_t ah[2][4], al[2][4], bh[4], bl[4];
#pragma unroll
            for (int mi = 0; mi < 2; mi++) {
                ldsm_x4(ah[mi][0], ah[mi][1], ah[mi][2], ah[mi][3], aAddr[mi] + kb);
                ldsm_x4(al[mi][0], al[mi][1], al[mi][2], al[mi][3], aAddr[mi] + kb + (OF_AL - OF_AH));
            }
            ldsm_x4(bh[0], bh[1], bh[2], bh[3], bAddr + kb);
            ldsm_x4(bl[0], bl[1], bl[2], bl[3], bAddr + kb + (OF_BL - OF_BH));
#pragma unroll
            for (int mi = 0; mi < 2; mi++)
#pragma unroll
                for (int nt = 0; nt < 2; nt++) {
                    mma16816(acc[mi][nt], ah[mi], bh[nt], bh[nt+2]);
                    mma16816(acc[mi][nt], ah[mi], bl[nt], bl[nt+2]);
                    mma16816(acc[mi][nt], al[mi], bh[nt], bh[nt+2]);
                }
        }
    }

#pragma unroll
    for (int mi = 0; mi < 2; mi++) {
        int rA = row0 + warp_m*32 + mi*16 + (lane >> 2);
#pragma unroll
        for (int nt = 0; nt < 2; nt++) {
            int col = n0 + warp_n*16 + nt*8 + (lane & 3)*2;
            if (rA < M)
                *reinterpret_cast<float2*>(C + (size_t)rA*N + col)
                    = make_float2(acc[mi][nt][0], acc[mi][nt][1]);
            if (rA + 8 < M)
                *reinterpret_cast<float2*>(C + (size_t)(rA + 8)*N + col)
                    = make_float2(acc[mi][nt][2], acc[mi][nt][3]);
        }
    }
}

// ---------------- one-pass row LayerNorm (float4, N<=768) -------------------
__global__ void ln_rows(const float* __restrict__ X, const float* __restrict__ g,
                        const float* __restrict__ b, float* __restrict__ Y, int N) {
    extern __shared__ float row[];
    __shared__ float red[256], red2[256];
    const int r = blockIdx.x, tid = threadIdx.x;
    const float4* x4 = reinterpret_cast<const float4*>(X + (size_t)r * N);
    float4* row4 = reinterpret_cast<float4*>(row);
    const int n4 = N >> 2;
    float s = 0.f, s2 = 0.f;
    for (int j = tid; j < n4; j += 256) {
        float4 v = x4[j];
        row4[j] = v;
        s  += v.x + v.y + v.z + v.w;
        s2 += v.x*v.x + v.y*v.y + v.z*v.z + v.w*v.w;
    }
    red[tid] = s; red2[tid] = s2; __syncthreads();
    for (int o = 128; o; o >>= 1) {
        if (tid < o) { red[tid] += red[tid+o]; red2[tid] += red2[tid+o]; }
        __syncthreads();
    }
    float mean = red[0] / (float)N;
    float rstd = rsqrtf(red2[0] / (float)N - mean*mean + EPS);
    const float4* g4 = reinterpret_cast<const float4*>(g);
    const float4* b4 = reinterpret_cast<const float4*>(b);
    float4* y4 = reinterpret_cast<float4*>(Y + (size_t)r * N);
    for (int j = tid; j < n4; j += 256) {
        float4 v = row4[j], gg = g4[j], bb = b4[j];
        v.x = (v.x - mean)*rstd*gg.x + bb.x;
        v.y = (v.y - mean)*rstd*gg.y + bb.y;
        v.z = (v.z - mean)*rstd*gg.z + bb.z;
        v.w = (v.w - mean)*rstd*gg.w + bb.w;
        y4[j] = v;
    }
}

// ---------------- mid-LN row statistics (no write-back of normalized mid) --
__global__ void mid_stats_kernel(const float* __restrict__ X) {
    __shared__ float red[256], red2[256];
    const int r = blockIdx.x, tid = threadIdx.x;
    const float4* x4 = reinterpret_cast<const float4*>(X + (size_t)r * GL);
    float s = 0.f, s2 = 0.f;
    for (int j = tid; j < GL/4; j += 256) {
        float4 v = x4[j];
        s  += v.x + v.y + v.z + v.w;
        s2 += v.x*v.x + v.y*v.y + v.z*v.z + v.w*v.w;
    }
    red[tid] = s; red2[tid] = s2; __syncthreads();
    for (int o = 128; o; o >>= 1) {
        if (tid < o) { red[tid] += red[tid+o]; red2[tid] += red2[tid+o]; }
        __syncthreads();
    }
    if (tid == 0) {
        float mean = red[0] / (float)GL;
        g_lnmu[r] = mean;
        g_lnrs[r] = rsqrtf(red2[0] / (float)GL - mean*mean + EPS);
    }
}

// ---------------- per-group Gram matrix + mean weight ----------------------
__global__ void prep_kernel(const float* __restrict__ Wconv) {
    __shared__ float s_w[64*65];
    const int g = blockIdx.x, tid = threadIdx.x;
    const int i = tid >> 2, j0 = (tid & 3) * 16;
    float acc[16];
#pragma unroll
    for (int p = 0; p < 16; p++) acc[p] = 0.f;
    float wsum = 0.f;
    for (int dt = 0; dt < 12; dt++) {
        __syncthreads();
        for (int idx = tid; idx < 4096; idx += 256) {
            int l = idx >> 6, c = idx & 63;
            s_w[l*65 + c] = Wconv[((size_t)(g*64 + l))*D_ + dt*64 + c];
        }
        __syncthreads();
        for (int c = 0; c < 64; c++) {
            float wi = s_w[i*65 + c];
#pragma unroll
            for (int p = 0; p < 16; p++) acc[p] += wi * s_w[(j0+p)*65 + c];
        }
        if (tid < 64)
            for (int c = 0; c < 64; c++) wsum += s_w[tid*65 + c];
    }
#pragma unroll
    for (int p = 0; p < 16; p++)
        g_Mg[(size_t)g*4096 + i*64 + j0 + p] = acc[p];
    if (tid < 64) g_wbar[g*64 + tid] = wsum * (1.0f / (float)D_);
}

// ---------------- fused sim + softmax --------------------------------------
__global__ void sim_softmax_kernel() {
    extern __shared__ float sm[];
    float* sq = sm;              // 32*129
    float* sk = sq + 32*129;     // 32*129
    float* ss = sk + 32*129;     // 32*257
    const int bh = blockIdx.y, b = bh / H_, h = bh - b*H_;
    const int i0 = blockIdx.x * 32;
    const int tid = threadIdx.x;

    for (int idx = tid; idx < 32*128; idx += 256) {
        int li = idx >> 7, d = idx & 127;
        sq[li*129 + d] = g_q[((size_t)(b*NQ + i0 + li))*D_ + h*DH + d];
    }
    const int li = tid >> 3, jq = tid & 7;
    for (int jt = 0; jt < 9; jt++) {
        int jb = jt * 32;
        __syncthreads();
        for (int idx = tid; idx < 32*128; idx += 256) {
            int lj = idx >> 7, d = idx & 127;
            int j = jb + lj;
            sk[lj*129 + d] = (j < NC) ? g_k[((size_t)(b*NC + j))*D_ + h*DH + d] : 0.f;
        }
        __syncthreads();
        const float* qrow = &sq[li*129];
        const float* k0 = &sk[(jq*4+0)*129];
        const float* k1 = &sk[(jq*4+1)*129];
        const float* k2 = &sk[(jq*4+2)*129];
        const float* k3 = &sk[(jq*4+3)*129];
        float a0=0.f, a1=0.f, a2=0.f, a3=0.f;
#pragma unroll 8
        for (int d = 0; d < 128; d++) {
            float qv = qrow[d];
            a0 += qv*k0[d]; a1 += qv*k1[d]; a2 += qv*k2[d]; a3 += qv*k3[d];
        }
        int jbb = jb + jq*4;
        if (jbb + 0 < NC) ss[li*NC + jbb + 0] = a0 * SCALE_QK;
        if (jbb + 1 < NC) ss[li*NC + jbb + 1] = a1 * SCALE_QK;
        if (jbb + 2 < NC) ss[li*NC + jbb + 2] = a2 * SCALE_QK;
        if (jbb + 3 < NC) ss[li*NC + jbb + 3] = a3 * SCALE_QK;
    }
    __syncthreads();
    const int warp = tid >> 5, lane = tid & 31;
    for (int rrow = warp; rrow < 32; rrow += 8) {
        float* r = &ss[rrow*NC];
        float mx = -1e30f;
        for (int j = lane; j < NC; j += 32) mx = fmaxf(mx, r[j]);
        for (int o = 16; o; o >>= 1) mx = fmaxf(mx, __shfl_xor_sync(0xffffffffu, mx, o));
        float sum = 0.f;
        for (int j = lane; j < NC; j += 32) { float e = __expf(r[j] - mx); r[j] = e; sum += e; }
        for (int o = 16; o; o >>= 1) sum += __shfl_xor_sync(0xffffffffu, sum, o);
        float inv = 1.f / sum;
        float* out = &g_attn[((size_t)(bh*NQ + i0 + rrow))*NC];
        for (int j = lane; j < NC; j += 32) out[j] = r[j] * inv;
    }
}

// ---------------- fused conv+LN+skip+attention-contract (512 threads) ------
// Applies mid-LN inline (raw mid + row stats + gv1/bv1 affine).
#define SFT 512
__global__ void __launch_bounds__(SFT) stageF_kernel(const float* __restrict__ ctx,
                              const float* __restrict__ Wconv,
                              const float* __restrict__ gv2,
                              const float* __restrict__ bv2,
                              const float* __restrict__ gv1,
                              const float* __restrict__ bv1,
                              __nv_bfloat16* __restrict__ oph,
                              __nv_bfloat16* __restrict__ opl) {
    extern __shared__ float sm[];
    float* s_mid = sm;                   // 257*65
    float* s_M   = s_mid + 257*65;       // 4096
    float* s_wb  = s_M   + 4096;         // 64
    float* s_mu  = s_wb  + 64;           // 257
    float* s_rs  = s_mu  + 257;          // 257
    float* s_a   = s_rs  + 257;          // 24*257
    float* s_c   = s_a   + 24*257;       // 24*64
    float* s_s1  = s_c   + 24*64;        // 24
    float* s_s0  = s_s1  + 24;           // 24
    float* s_ctx = s_s0  + 24;           // 257*33
    float* s_W   = s_ctx + 257*33;       // 64*33
    float* s_red = s_W   + 64*33;        // 16*4*32
    float* s_lmu = s_red + 2048;         // 257
    float* s_lrs = s_lmu + 257;          // 257

    const int g = blockIdx.x, b = blockIdx.y;
    const int tid = threadIdx.x;

    for (int n = tid; n < NC; n += SFT) {
        s_lmu[n] = g_lnmu[b*NC + n];
        s_lrs[n] = g_lnrs[b*NC + n];
    }
    __syncthreads();

    // inline LN of mid while loading: l = tid&63 is loop-invariant
    {
        const float gvl = gv1[g*64 + (tid & 63)];
        const float bvl = bv1[g*64 + (tid & 63)];
        for (int i = tid; i < NC*LORA; i += SFT) {
            int n = i >> 6, l = i & 63;
            float raw = g_mid[((size_t)(b*NC + n))*GL + g*LORA + l];
            s_mid[n*65 + l] = (raw - s_lmu[n]) * s_lrs[n] * gvl + bvl;
        }
    }
    for (int i = tid; i < 4096; i += SFT) s_M[i] = g_Mg[(size_t)g*4096 + i];
    if (tid < 64) s_wb[tid] = g_wbar[g*64 + tid];
    for (int i = tid; i < 24*NC; i += SFT) {
        int hr = i / NC, n = i - hr*NC;
        int h = hr >> 2, r = hr & 3;
        s_a[hr*NC + n] = g_attn[((size_t)((b*H_ + h)*NQ + (r*G_ + g)))*NC + n];
    }
    __syncthreads();

    {
        const int half = tid & 1;
        const int l0 = half * 32;
#pragma unroll
        for (int nb = 0; nb < 2; nb++) {
            int n = (tid >> 1) + nb * 256;
            float mu = 0.f, qf = 0.f;
            if (n < NC) {
                const float* m = &s_mid[n*65];
#pragma unroll 8
                for (int l = l0; l < l0 + 32; l++) mu += m[l]*s_wb[l];
                for (int i2 = l0; i2 < l0 + 32; i2++) {
                    const float* Mi = &s_M[i2*64];
                    float t = 0.f;
#pragma unroll 16
                    for (int j = 0; j < 64; j++) t += Mi[j]*m[j];
                    qf += m[i2]*t;
                }
            }
            mu += __shfl_xor_sync(0xffffffffu, mu, 1);
            qf += __shfl_xor_sync(0xffffffffu, qf, 1);
            if (n < NC && half == 0) {
                float var = qf * (1.0f/(float)D_) - mu*mu;
                s_mu[n] = mu;
                s_rs[n] = rsqrtf(var + EPS);
            }
        }
    }
    __syncthreads();

    for (int idx = tid; idx < 24*66; idx += SFT) {
        int hr = idx / 66, j = idx - hr*66;
        const float* a = &s_a[hr*NC];
        float acc = 0.f;
        if (j < 64) {
            for (int n = 0; n < NC; n++) acc += a[n]*s_rs[n]*s_mid[n*65 + j];
            s_c[hr*64 + j] = acc;
        } else if (j == 64) {
            for (int n = 0; n < NC; n++) acc += a[n]*s_rs[n]*s_mu[n];
            s_s1[hr] = acc;
        } else {
            for (int n = 0; n < NC; n++) acc += a[n];
            s_s0[hr] = acc;
        }
    }
    __syncthreads();

    const int dc = tid & 31, seg = tid >> 5;   // 16 segments
    for (int h = 0; h < H_; h++) {
        for (int dt = 0; dt < 4; dt++) {
            int dbase = h*DH + dt*32;
            __syncthreads();
            for (int i = tid; i < NC*32; i += SFT) {
                int n = i >> 5, c = i & 31;
                s_ctx[n*33 + c] = ctx[((size_t)(b*NC + n))*D_ + dbase + c];
            }
            for (int i = tid; i < 64*32; i += SFT) {
                int l = i >> 5, c = i & 31;
                s_W[l*33 + c] = Wconv[((size_t)(g*64 + l))*D_ + dbase + c];
            }
            __syncthreads();
            float a0=0.f, a1=0.f, a2=0.f, a3=0.f;
            for (int n = seg; n < NC; n += 16) {
                float cv = s_ctx[n*33 + dc];
                a0 += s_a[(h*4+0)*NC + n]*cv;
                a1 += s_a[(h*4+1)*NC + n]*cv;
                a2 += s_a[(h*4+2)*NC + n]*cv;
                a3 += s_a[(h*4+3)*NC + n]*cv;
            }
            s_red[(seg*4+0)*32 + dc] = a0;
            s_red[(seg*4+1)*32 + dc] = a1;
            s_red[(seg*4+2)*32 + dc] = a2;
            s_red[(seg*4+3)*32 + dc] = a3;
            __syncthreads();
            if (tid < 128) {
                const int r = tid >> 5;
                int dglob = dbase + dc;
                float gvd = gv2[dglob], bvd = bv2[dglob];
                float cs = 0.f;
#pragma unroll
                for (int s = 0; s < 16; s++) cs += s_red[(s*4+r)*32 + dc];
                int hr = h*4 + r;
                const float* c = &s_c[hr*64];
                float wd = 0.f;
#pragma unroll 16
                for (int l = 0; l < 64; l++) wd += c[l]*s_W[l*33 + dc];
                float o = gvd*(wd - s_s1[hr]) + bvd*s_s0[hr] + cs;
                size_t oidx = ((size_t)(b*NQ + r*G_ + g))*D_ + dglob;
                __nv_bfloat16 hv = __float2bfloat16_rn(o);
                oph[oidx] = hv;
                opl[oidx] = __float2bfloat16_rn(o - __bfloat162float(hv));
            }
        }
    }
}

// ---------------- launch ----------------------------------------------------
extern "C" void kernel_launch(void* const* d_in, const int* in_sizes, int n_in,
                              void* d_out, int out_size) {
    const float* x     = (const float*)d_in[0];
    const float* ctx   = (const float*)d_in[1];
    const float* Wq    = (const float*)d_in[2];
    const float* gq    = (const float*)d_in[3];
    const float* bq    = (const float*)d_in[4];
    const float* Wk    = (const float*)d_in[5];
    const float* gk    = (const float*)d_in[6];
    const float* bk    = (const float*)d_in[7];
    const float* Wv    = (const float*)d_in[8];
    const float* gv1   = (const float*)d_in[9];
    const float* bv1   = (const float*)d_in[10];
    const float* Wconv = (const float*)d_in[11];
    const float* gv2   = (const float*)d_in[12];
    const float* bv2   = (const float*)d_in[13];
    const float* Wo    = (const float*)d_in[14];
    const float* go    = (const float*)d_in[15];
    const float* bo    = (const float*)d_in[16];
    float* out = (float*)d_out;

    float *pq, *pk, *pmid;
    cudaGetSymbolAddress((void**)&pq, g_q);
    cudaGetSymbolAddress((void**)&pk, g_k);
    cudaGetSymbolAddress((void**)&pmid, g_mid);
    __nv_bfloat16 *xh,*xl,*ch,*cl,*oph,*opl,*wqh,*wql,*wkh,*wkl,*woh,*wol,*wvh,*wvl;
    cudaGetSymbolAddress((void**)&xh,  s_xh);  cudaGetSymbolAddress((void**)&xl,  s_xl);
    cudaGetSymbolAddress((void**)&ch,  s_ch);  cudaGetSymbolAddress((void**)&cl,  s_cl);
    cudaGetSymbolAddress((void**)&oph, s_oph); cudaGetSymbolAddress((void**)&opl, s_opl);
    cudaGetSymbolAddress((void**)&wqh, s_wqh); cudaGetSymbolAddress((void**)&wql, s_wql);
    cudaGetSymbolAddress((void**)&wkh, s_wkh); cudaGetSymbolAddress((void**)&wkl, s_wkl);
    cudaGetSymbolAddress((void**)&woh, s_woh); cudaGetSymbolAddress((void**)&wol, s_wol);
    cudaGetSymbolAddress((void**)&wvh, s_wvh); cudaGetSymbolAddress((void**)&wvl, s_wvl);

    const int SIM_SMEM = (32*129*2 + 32*257) * 4;
    const int SF_SMEM  = (257*65 + 4096 + 64 + 257 + 257 + 24*257
                          + 24*64 + 48 + 257*33 + 64*33 + 2048 + 514) * 4;
    cudaFuncSetAttribute(sim_softmax_kernel,
                         cudaFuncAttributeMaxDynamicSharedMemorySize, SIM_SMEM);
    cudaFuncSetAttribute(stageF_kernel,
                         cudaFuncAttributeMaxDynamicSharedMemorySize, SF_SMEM);
    cudaFuncSetAttribute(hmma_gemm,
                         cudaFuncAttributeMaxDynamicSharedMemorySize, HG_SMEM);

    // 0 split ctx, 1 splitT Wv, 2 split x, 3 mid GEMM (profiled)
    split_kernel<<<(B_*NC*D_/4 + 255)/256, 256>>>(ctx, ch, cl, B_*NC*D_/4);
    splitT_kernel<<<dim3(GL/32, D_/64), 256>>>(Wv, wvh, wvl, D_, GL);
    split_kernel<<<(B_*NQ*D_/4 + 255)/256, 256>>>(x, xh, xl, B_*NQ*D_/4);
    hmma_gemm<<<dim3(GL/64, 17), 256, HG_SMEM>>>(ch, cl, wvh, wvl, pmid, B_*NC, GL, D_);
    mid_stats_kernel<<<B_*NC, 256>>>(pmid);
    // q / k
    splitT_kernel<<<dim3(D_/32, D_/64), 256>>>(Wq, wqh, wql, D_, D_);
    hmma_gemm<<<dim3(D_/64, 26), 256, HG_SMEM>>>(xh, xl, wqh, wql, pq, B_*NQ, D_, D_);
    ln_rows<<<B_*NQ, 256, D_*4>>>(pq, gq, bq, pq, D_);
    splitT_kernel<<<dim3(D_/32, D_/64), 256>>>(Wk, wkh, wkl, D_, D_);
    hmma_gemm<<<dim3(D_/64, 17), 256, HG_SMEM>>>(ch, cl, wkh, wkl, pk, B_*NC, D_, D_);
    ln_rows<<<B_*NC, 256, D_*4>>>(pk, gk, bk, pk, D_);
    // rest
    splitT_kernel<<<dim3(D_/32, D_/64), 256>>>(Wo, woh, wol, D_, D_);
    prep_kernel<<<G_, 256>>>(Wconv);
    sim_softmax_kernel<<<dim3(NQ/32, B_*H_), 256, SIM_SMEM>>>();
    stageF_kernel<<<dim3(G_, B_), SFT, SF_SMEM>>>(ctx, Wconv, gv2, bv2, gv1, bv1, oph, opl);
    hmma_gemm<<<dim3(D_/64, 26), 256, HG_SMEM>>>(oph, opl, woh, wol, pq, B_*NQ, D_, D_);
    ln_rows<<<B_*NQ, 256, D_*4>>>(pq, go, bo, out, D_);
}

// round 14
// speedup vs baseline: 1.7197x; 1.7133x over previous
#include <cuda_runtime.h>
#include <cuda_bf16.h>
#include <cstdint>

#define B_   4
#define NQ   416
#define NC   257
#define D_   768
#define H_   6
#define DH   128
#define G_   104
#define R_   4
#define LORA 64
#define GL   (G_*LORA)   // 6656
#define BH   (B_*H_)     // 24
#define EPS  1e-5f
#define SCALE_QK 0.08838834764831843f   // DH^-0.5 (applied fully to q)

// ---------------- scratch (device globals: allocation-free) ----------------
__device__ __align__(16) float g_q[B_*NQ*D_];
__device__ __align__(16) float g_k[B_*NC*D_];
__device__ __align__(16) float g_mid[B_*NC*GL];      // RAW (pre-LN) mid
__device__ __align__(16) float g_attn[BH*NQ*NC];     // f32 softmax (for F1)
__device__ __align__(16) float g_sim[BH*NQ*NC];
__device__ __align__(16) float g_skip[BH*NQ*DH];
__device__ __align__(16) float g_Mg[G_*LORA*LORA];
__device__ __align__(16) float g_wbar[G_*LORA];
__device__ __align__(16) float g_lnmu[B_*NC];
__device__ __align__(16) float g_lnrs[B_*NC];
__device__ __align__(16) float g_c[B_*G_*24*64];
__device__ __align__(16) float g_s1[B_*G_*24];
__device__ __align__(16) float g_s0[B_*G_*24];

// bf16 hi/lo operands
__device__ __align__(16) __nv_bfloat16 s_xh[B_*NQ*D_],  s_xl[B_*NQ*D_];
__device__ __align__(16) __nv_bfloat16 s_ch[B_*NC*D_],  s_cl[B_*NC*D_];
__device__ __align__(16) __nv_bfloat16 s_oph[B_*NQ*D_], s_opl[B_*NQ*D_];
__device__ __align__(16) __nv_bfloat16 s_wqh[D_*D_],  s_wql[D_*D_];
__device__ __align__(16) __nv_bfloat16 s_wkh[D_*D_],  s_wkl[D_*D_];
__device__ __align__(16) __nv_bfloat16 s_woh[D_*D_],  s_wol[D_*D_];
__device__ __align__(16) __nv_bfloat16 s_wvh[(size_t)D_*GL], s_wvl[(size_t)D_*GL];
// attention-path operands (padded: M 448/group, K 320)
__device__ __align__(16) __nv_bfloat16 s_qh2[BH*448*DH],  s_ql2[BH*448*DH];
__device__ __align__(16) __nv_bfloat16 s_kh2[BH*320*DH],  s_kl2[BH*320*DH];
__device__ __align__(16) __nv_bfloat16 s_cth[BH*DH*320],  s_ctl[BH*DH*320];
__device__ __align__(16) __nv_bfloat16 s_ath[(size_t)BH*448*320], s_atl[(size_t)BH*448*320];

// ---------------- helpers ---------------------------------------------------
__device__ __forceinline__ uint32_t smem_u32(const void* p) {
    uint32_t a;
    asm("{ .reg .u64 t; cvta.to.shared.u64 t, %1; cvt.u32.u64 %0, t; }" : "=r"(a) : "l"(p));
    return a;
}
__device__ __forceinline__ void ldsm_x4(uint32_t& r0, uint32_t& r1,
                                        uint32_t& r2, uint32_t& r3, uint32_t addr) {
    asm volatile("ldmatrix.sync.aligned.m8n8.x4.shared.b16 {%0,%1,%2,%3}, [%4];"
                 : "=r"(r0), "=r"(r1), "=r"(r2), "=r"(r3) : "r"(addr));
}
__device__ __forceinline__ void mma16816(float* d, const uint32_t* a,
                                         uint32_t b0, uint32_t b1) {
    asm volatile("mma.sync.aligned.m16n8k16.row.col.f32.bf16.bf16.f32 "
                 "{%0,%1,%2,%3}, {%4,%5,%6,%7}, {%8,%9}, {%0,%1,%2,%3};"
                 : "+f"(d[0]), "+f"(d[1]), "+f"(d[2]), "+f"(d[3])
                 : "r"(a[0]), "r"(a[1]), "r"(a[2]), "r"(a[3]), "r"(b0), "r"(b1));
}
#define CP16(dst, src) asm volatile("cp.async.ca.shared.global [%0], [%1], 16;" :: "r"(dst), "l"(src))
#define CP_COMMIT()    asm volatile("cp.async.commit_group;" ::: "memory")
#define CP_WAIT0()     asm volatile("cp.async.wait_group 0;" ::: "memory")

__device__ __forceinline__ void split2(float v, __nv_bfloat16& h, __nv_bfloat16& l) {
    h = __float2bfloat16_rn(v);
    l = __float2bfloat16_rn(v - __bfloat162float(h));
}

// ---------------- split kernels (fp32 -> bf16 hi/lo) ------------------------
__global__ void split_kernel(const float* __restrict__ X,
                             __nv_bfloat16* __restrict__ hi,
                             __nv_bfloat16* __restrict__ lo, int n4) {
    int i = blockIdx.x * 256 + threadIdx.x;
    if (i >= n4) return;
    float4 v = reinterpret_cast<const float4*>(X)[i];
    __nv_bfloat16 h0, h1, h2, h3, l0, l1, l2, l3;
    split2(v.x, h0, l0); split2(v.y, h1, l1); split2(v.z, h2, l2); split2(v.w, h3, l3);
    reinterpret_cast<__nv_bfloat162*>(hi)[i*2]   = __halves2bfloat162(h0, h1);
    reinterpret_cast<__nv_bfloat162*>(hi)[i*2+1] = __halves2bfloat162(h2, h3);
    reinterpret_cast<__nv_bfloat162*>(lo)[i*2]   = __halves2bfloat162(l0, l1);
    reinterpret_cast<__nv_bfloat162*>(lo)[i*2+1] = __halves2bfloat162(l2, l3);
}

// W[k][n] fp32 -> WtHi/Lo[n][k] bf16: 64k x 32n tiles, 16B coalesced stores
__global__ void splitT_kernel(const float* __restrict__ W,
                              __nv_bfloat16* __restrict__ hiT,
                              __nv_bfloat16* __restrict__ loT, int K, int N) {
    __shared__ float t[64][33];
    const int nb = blockIdx.x * 32, kb = blockIdx.y * 64;
    const int tid = threadIdx.x;
    for (int i = tid; i < 2048; i += 256) {
        int ky = i >> 5, nx = i & 31;
        t[ky][nx] = W[(size_t)(kb + ky) * N + nb + nx];
    }
    __syncthreads();
    const int ny = tid >> 3, k8 = (tid & 7) * 8;
    __align__(16) __nv_bfloat16 hv[8], lv[8];
#pragma unroll
    for (int j = 0; j < 8; j++) split2(t[k8 + j][ny], hv[j], lv[j]);
    size_t o = (size_t)(nb + ny) * K + kb + k8;
    *reinterpret_cast<uint4*>(hiT + o) = *reinterpret_cast<const uint4*>(hv);
    *reinterpret_cast<uint4*>(loT + o) = *reinterpret_cast<const uint4*>(lv);
}

// q (post-LN) -> per-head padded rows [bh,448,128], scaled by DH^-0.5
__global__ void split_head_q(const float* __restrict__ Q,
                             __nv_bfloat16* __restrict__ qh,
                             __nv_bfloat16* __restrict__ ql) {
    int idx = blockIdx.x * 256 + threadIdx.x;           // B*NQ*D/4
    if (idx >= B_*NQ*D_/4) return;
    int flat = idx * 4;
    int b = flat / (NQ*D_);
    int rem = flat - b*NQ*D_;
    int i = rem / D_;
    int c = rem - i*D_;
    int h = c >> 7, d = c & 127;
    float4 v = reinterpret_cast<const float4*>(Q)[idx];
    v.x *= SCALE_QK; v.y *= SCALE_QK; v.z *= SCALE_QK; v.w *= SCALE_QK;
    __nv_bfloat16 h0,h1,h2,h3,l0,l1,l2,l3;
    split2(v.x,h0,l0); split2(v.y,h1,l1); split2(v.z,h2,l2); split2(v.w,h3,l3);
    size_t o = ((size_t)((b*H_ + h)*448 + i))*DH + d;
    *reinterpret_cast<__nv_bfloat162*>(qh + o)     = __halves2bfloat162(h0, h1);
    *reinterpret_cast<__nv_bfloat162*>(qh + o + 2) = __halves2bfloat162(h2, h3);
    *reinterpret_cast<__nv_bfloat162*>(ql + o)     = __halves2bfloat162(l0, l1);
    *reinterpret_cast<__nv_bfloat162*>(ql + o + 2) = __halves2bfloat162(l2, l3);
}

// k (post-LN) -> per-head padded Bt rows [bh,320,128], zero rows >=257
__global__ void split_head_k(const float* __restrict__ Kp,
                             __nv_bfloat16* __restrict__ kh,
                             __nv_bfloat16* __restrict__ kl) {
    int idx = blockIdx.x * 256 + threadIdx.x;           // BH*320*128/4
    if (idx >= BH*320*DH/4) return;
    int flat = idx * 4;
    int bh = flat / (320*DH);
    int rem = flat - bh*320*DH;
    int n = rem >> 7, d = rem & 127;
    int b = bh / H_, h = bh - b*H_;
    float4 v = make_float4(0.f, 0.f, 0.f, 0.f);
    if (n < NC)
        v = *reinterpret_cast<const float4*>(Kp + ((size_t)(b*NC + n))*D_ + h*DH + d);
    __nv_bfloat16 h0,h1,h2,h3,l0,l1,l2,l3;
    split2(v.x,h0,l0); split2(v.y,h1,l1); split2(v.z,h2,l2); split2(v.w,h3,l3);
    size_t o = ((size_t)bh*320 + n)*DH + d;
    *reinterpret_cast<__nv_bfloat162*>(kh + o)     = __halves2bfloat162(h0, h1);
    *reinterpret_cast<__nv_bfloat162*>(kh + o + 2) = __halves2bfloat162(h2, h3);
    *reinterpret_cast<__nv_bfloat162*>(kl + o)     = __halves2bfloat162(l0, l1);
    *reinterpret_cast<__nv_bfloat162*>(kl + o + 2) = __halves2bfloat162(l2, l3);
}

// ctx -> transposed per-head Bt [bh, 128(dh), 320(n)], zero cols >=257
// FIXED (R13 bug): 32-wide tile -> n4 = (tid&7)*4, 4 elems/thread, uint2 store.
__global__ void split_ctxT(const float* __restrict__ ctx,
                           __nv_bfloat16* __restrict__ cth,
                           __nv_bfloat16* __restrict__ ctl) {
    __shared__ float t[32][33];
    const int nb = blockIdx.x * 32, db = blockIdx.y * 32, bh = blockIdx.z;
    const int b = bh / H_, h = bh - b*H_;
    const int tid = threadIdx.x;
    for (int i = tid; i < 1024; i += 256) {
        int nn = i >> 5, dd = i & 31;
        int n = nb + nn;
        t[nn][dd] = (n < NC) ? ctx[((size_t)(b*NC + n))*D_ + h*DH + db + dd] : 0.f;
    }
    __syncthreads();
    const int dr = tid >> 3, n4 = (tid & 7) * 4;   // 32 d-rows x 8 col-groups of 4
    __align__(8) __nv_bfloat16 hv[4], lv[4];
#pragma unroll
    for (int j = 0; j < 4; j++) split2(t[n4 + j][dr], hv[j], lv[j]);
    size_t o = ((size_t)bh*DH + db + dr)*320 + nb + n4;
    *reinterpret_cast<uint2*>(cth + o) = *reinterpret_cast<const uint2*>(hv);
    *reinterpret_cast<uint2*>(ctl + o) = *reinterpret_cast<const uint2*>(lv);
}

// ---------------- batched 3xBF16 HMMA GEMM, 64x64 tile, 128 thr, 1-buf -----
// C[grp][i,n] = A[grp][i,:K] @ Bt[grp][n,:K]^T ; per-group row clamp on A.
#define AST   72
#define OF_AH 0
#define OF_AL 9216
#define OF_BH 18432
#define OF_BL 27648
#define HG_SMEM 36864        // single buffer -> 6 CTAs/SM

__global__ void __launch_bounds__(128) hmma_gemm(
    const __nv_bfloat16* __restrict__ Ah, const __nv_bfloat16* __restrict__ Al,
    const __nv_bfloat16* __restrict__ Bh, const __nv_bfloat16* __restrict__ Bl,
    float* __restrict__ C, int K, int tilesM, int Mvalid, int Nvalid, int ldc,
    size_t aStride, size_t bStride, size_t cStride) {
    extern __shared__ __align__(128) char smem[];
    const uint32_t sb = smem_u32(smem);
    const int tid = threadIdx.x, lane = tid & 31, warp = tid >> 5;
    const int warp_m = warp & 1, warp_n = warp >> 1;   // 2x2 grid, warp tile 32x32
    const int grp = blockIdx.y / tilesM;
    const int row0 = (blockIdx.y - grp*tilesM) * 64;
    const int n0 = blockIdx.x * 64;
    const __nv_bfloat16* Ahg = Ah + (size_t)grp * aStride;
    const __nv_bfloat16* Alg = Al + (size_t)grp * aStride;
    const __nv_bfloat16* Bhg = Bh + (size_t)grp * bStride;
    const __nv_bfloat16* Blg = Bl + (size_t)grp * bStride;
    float* Cg = C + (size_t)grp * cStride;

    float acc[2][4][4];
#pragma unroll
    for (int mi = 0; mi < 2; mi++)
#pragma unroll
        for (int nt = 0; nt < 4; nt++)
#pragma unroll
            for (int r = 0; r < 4; r++) acc[mi][nt][r] = 0.f;

    uint32_t aAddr[2], bAddr[2];
#pragma unroll
    for (int mi = 0; mi < 2; mi++)
        aAddr[mi] = sb + OF_AH
                  + (uint32_t)((warp_m*32 + mi*16 + (lane & 15)) * (AST*2))
                  + (uint32_t)((lane >> 4) * 16);
#pragma unroll
    for (int g = 0; g < 2; g++)
        bAddr[g] = sb + OF_BH
                 + (uint32_t)((warp_n*32 + g*16 + (lane & 15)) * (AST*2))
                 + (uint32_t)((lane >> 4) * 16);

    const int NCH = K >> 6;
    for (int kc = 0; kc < NCH; kc++) {
        const int k0 = kc << 6;
        __syncthreads();
#pragma unroll
        for (int t = 0; t < 4; t++) {
            int idx = t * 128 + tid;
            int r = idx >> 3, seg = idx & 7;
            int rl = row0 + r; if (rl >= Mvalid) rl = Mvalid - 1;
            size_t so = (size_t)rl * K + k0 + seg * 8;
            uint32_t dof = (uint32_t)(r * (AST*2) + seg * 16);
            CP16(sb + OF_AH + dof, Ahg + so);
            CP16(sb + OF_AL + dof, Alg + so);
        }
#pragma unroll
        for (int t = 0; t < 4; t++) {
            int idx = t * 128 + tid;
            int r = idx >> 3, seg = idx & 7;
            size_t so = (size_t)(n0 + r) * K + k0 + seg * 8;
            uint32_t dof = (uint32_t)(r * (AST*2) + seg * 16);
            CP16(sb + OF_BH + dof, Bhg + so);
            CP16(sb + OF_BL + dof, Blg + so);
        }
        CP_COMMIT();
        CP_WAIT0();
        __syncthreads();
#pragma unroll
        for (int ks = 0; ks < 4; ks++) {
            const uint32_t kb = (uint32_t)(ks * 32);
            uint32_t ah[2][4], al[2][4], bh[2][4], bl[2][4];
#pragma unroll
            for (int mi = 0; mi < 2; mi++) {
                ldsm_x4(ah[mi][0], ah[mi][1], ah[mi][2], ah[mi][3], aAddr[mi] + kb);
                ldsm_x4(al[mi][0], al[mi][1], al[mi][2], al[mi][3], aAddr[mi] + kb + (OF_AL - OF_AH));
            }
#pragma unroll
            for (int g = 0; g < 2; g++) {
                ldsm_x4(bh[g][0], bh[g][1], bh[g][2], bh[g][3], bAddr[g] + kb);
                ldsm_x4(bl[g][0], bl[g][1], bl[g][2], bl[g][3], bAddr[g] + kb + (OF_BL - OF_BH));
            }
#pragma unroll
            for (int mi = 0; mi < 2; mi++)
#pragma unroll
                for (int nt = 0; nt < 4; nt++) {
                    const int g = nt >> 1, j = nt & 1;
                    mma16816(acc[mi][nt], ah[mi], bh[g][j], bh[g][j+2]);
                    mma16816(acc[mi][nt], ah[mi], bl[g][j], bl[g][j+2]);
                    mma16816(acc[mi][nt], al[mi], bh[g][j], bh[g][j+2]);
                }
        }
    }

#pragma unroll
    for (int mi = 0; mi < 2; mi++) {
        int rA = row0 + warp_m*32 + mi*16 + (lane >> 2);
#pragma unroll
        for (int nt = 0; nt < 4; nt++) {
            int col = n0 + warp_n*32 + nt*8 + (lane & 3)*2;
            if (rA < Mvalid) {
                float* cr = Cg + (size_t)rA * ldc;
                if (col < Nvalid)     cr[col]     = acc[mi][nt][0];
                if (col + 1 < Nvalid) cr[col + 1] = acc[mi][nt][1];
            }
            if (rA + 8 < Mvalid) {
                float* cr = Cg + (size_t)(rA + 8) * ldc;
                if (col < Nvalid)     cr[col]     = acc[mi][nt][2];
                if (col + 1 < Nvalid) cr[col + 1] = acc[mi][nt][3];
            }
        }
    }
}

// ---------------- one-pass row LayerNorm (float4) ---------------------------
__global__ void ln_rows(const float* __restrict__ X, const float* __restrict__ g,
                        const float* __restrict__ b, float* __restrict__ Y, int N) {
    extern __shared__ float row[];
    __shared__ float red[256], red2[256];
    const int r = blockIdx.x, tid = threadIdx.x;
    const float4* x4 = reinterpret_cast<const float4*>(X + (size_t)r * N);
    float4* row4 = reinterpret_cast<float4*>(row);
    const int n4 = N >> 2;
    float s = 0.f, s2 = 0.f;
    for (int j = tid; j < n4; j += 256) {
        float4 v = x4[j];
        row4[j] = v;
        s  += v.x + v.y + v.z + v.w;
        s2 += v.x*v.x + v.y*v.y + v.z*v.z + v.w*v.w;
    }
    red[tid] = s; red2[tid] = s2; __syncthreads();
    for (int o = 128; o; o >>= 1) {
        if (tid < o) { red[tid] += red[tid+o]; red2[tid] += red2[tid+o]; }
        __syncthreads();
    }
    float mean = red[0] / (float)N;
    float rstd = rsqrtf(red2[0] / (float)N - mean*mean + EPS);
    const float4* g4 = reinterpret_cast<const float4*>(g);
    const float4* b4 = reinterpret_cast<const float4*>(b);
    float4* y4 = reinterpret_cast<float4*>(Y + (size_t)r * N);
    for (int j = tid; j < n4; j += 256) {
        float4 v = row4[j], gg = g4[j], bb = b4[j];
        v.x = (v.x - mean)*rstd*gg.x + bb.x;
        v.y = (v.y - mean)*rstd*gg.y + bb.y;
        v.z = (v.z - mean)*rstd*gg.z + bb.z;
        v.w = (v.w - mean)*rstd*gg.w + bb.w;
        y4[j] = v;
    }
}

// ---------------- mid-LN row statistics ------------------------------------
__global__ void mid_stats_kernel(const float* __restrict__ X) {
    __shared__ float red[256], red2[256];
    const int r = blockIdx.x, tid = threadIdx.x;
    const float4* x4 = reinterpret_cast<const float4*>(X + (size_t)r * GL);
    float s = 0.f, s2 = 0.f;
    for (int j = tid; j < GL/4; j += 256) {
        float4 v = x4[j];
        s  += v.x + v.y + v.z + v.w;
        s2 += v.x*v.x + v.y*v.y + v.z*v.z + v.w*v.w;
    }
    red[tid] = s; red2[tid] = s2; __syncthreads();
    for (int o = 128; o; o >>= 1) {
        if (tid < o) { red[tid] += red[tid+o]; red2[tid] += red2[tid+o]; }
        __syncthreads();
    }
    if (tid == 0) {
        float mean = red[0] / (float)GL;
        g_lnmu[r] = mean;
        g_lnrs[r] = rsqrtf(red2[0] / (float)GL - mean*mean + EPS);
    }
}

// ---------------- per-group Gram matrix + mean weight ----------------------
__global__ void prep_kernel(const float* __restrict__ Wconv) {
    __shared__ float s_w[64*65];
    const int g = blockIdx.x, tid = threadIdx.x;
    const int i = tid >> 2, j0 = (tid & 3) * 16;
    float acc[16];
#pragma unroll
    for (int p = 0; p < 16; p++) acc[p] = 0.f;
    float wsum = 0.f;
    for (int dt = 0; dt < 12; dt++) {
        __syncthreads();
        for (int idx = tid; idx < 4096; idx += 256) {
            int l = idx >> 6, c = idx & 63;
            s_w[l*65 + c] = Wconv[((size_t)(g*64 + l))*D_ + dt*64 + c];
        }
        __syncthreads();
        for (int c = 0; c < 64; c++) {
            float wi = s_w[i*65 + c];
#pragma unroll
            for (int p = 0; p < 16; p++) acc[p] += wi * s_w[(j0+p)*65 + c];
        }
        if (tid < 64)
            for (int c = 0; c < 64; c++) wsum += s_w[tid*65 + c];
    }
#pragma unroll
    for (int p = 0; p < 16; p++)
        g_Mg[(size_t)g*4096 + i*64 + j0 + p] = acc[p];
    if (tid < 64) g_wbar[g*64 + tid] = wsum * (1.0f / (float)D_);
}

// ---------------- softmax (from g_sim; writes f32 attn + bf16 hi/lo padded) -
__global__ void softmax_kernel(const float* __restrict__ sim,
                               float* __restrict__ attn,
                               __nv_bfloat16* __restrict__ ath,
                               __nv_bfloat16* __restrict__ atl) {
    const int bh = blockIdx.y, i0 = blockIdx.x * 32;
    const int warp = threadIdx.x >> 5, lane = threadIdx.x & 31;
    const __nv_bfloat16 zb = __float2bfloat16_rn(0.f);
    for (int rr = warp; rr < 32; rr += 8) {
        int i = i0 + rr;
        const float* srow = sim + ((size_t)bh*NQ + i)*NC;
        float v[9];
        float mx = -1e30f;
#pragma unroll
        for (int jj = 0; jj < 9; jj++) {
            int j = jj*32 + lane;
            v[jj] = (j < NC) ? srow[j] : -1e30f;
            mx = fmaxf(mx, v[jj]);
        }
        for (int o = 16; o; o >>= 1) mx = fmaxf(mx, __shfl_xor_sync(0xffffffffu, mx, o));
        float sum = 0.f;
#pragma unroll
        for (int jj = 0; jj < 9; jj++) { v[jj] = __expf(v[jj] - mx); sum += v[jj]; }
        for (int o = 16; o; o >>= 1) sum += __shfl_xor_sync(0xffffffffu, sum, o);
        float inv = 1.f / sum;
        float* arow = attn + ((size_t)bh*NQ + i)*NC;
        __nv_bfloat16* hrow = ath + ((size_t)bh*448 + i)*320;
        __nv_bfloat16* lrow = atl + ((size_t)bh*448 + i)*320;
#pragma unroll
        for (int jj = 0; jj < 9; jj++) {
            int j = jj*32 + lane;
            if (j < NC) {
                float e = v[jj] * inv;
                arow[j] = e;
                __nv_bfloat16 hv, lv;
                split2(e, hv, lv);
                hrow[j] = hv; lrow[j] = lv;
            } else if (j < 320) {
                hrow[j] = zb; lrow[j] = zb;
            }
        }
        // pad columns 288..319 (jj==9 range)
        int j9 = 288 + lane;
        if (j9 < 320) { hrow[j9] = zb; lrow[j9] = zb; }
    }
}

// ---------------- F1: mid quad-form + c/s1/s0 (no ctx loop) -----------------
#define SFT 512
#define SF1_SMEM ((257*65 + 4096 + 64 + 257 + 257 + 24*257 + 257 + 257) * 4)
__global__ void __launch_bounds__(SFT) stageF1_kernel(
    const float* __restrict__ gv1, const float* __restrict__ bv1,
    float* __restrict__ gc, float* __restrict__ gs1, float* __restrict__ gs0) {
    extern __shared__ float sm[];
    float* s_mid = sm;                   // 257*65
    float* s_M   = s_mid + 257*65;       // 4096
    float* s_wb  = s_M   + 4096;         // 64
    float* s_mu  = s_wb  + 64;           // 257
    float* s_rs  = s_mu  + 257;          // 257
    float* s_a   = s_rs  + 257;          // 24*257
    float* s_lmu = s_a   + 24*257;       // 257
    float* s_lrs = s_lmu + 257;          // 257

    const int g = blockIdx.x, b = blockIdx.y;
    const int tid = threadIdx.x;

    for (int n = tid; n < NC; n += SFT) {
        s_lmu[n] = g_lnmu[b*NC + n];
        s_lrs[n] = g_lnrs[b*NC + n];
    }
    __syncthreads();
    {
        const float gvl = gv1[g*64 + (tid & 63)];
        const float bvl = bv1[g*64 + (tid & 63)];
        for (int i = tid; i < NC*LORA; i += SFT) {
            int n = i >> 6, l = i & 63;
            float raw = g_mid[((size_t)(b*NC + n))*GL + g*LORA + l];
            s_mid[n*65 + l] = (raw - s_lmu[n]) * s_lrs[n] * gvl + bvl;
        }
    }
    for (int i = tid; i < 4096; i += SFT) s_M[i] = g_Mg[(size_t)g*4096 + i];
    if (tid < 64) s_wb[tid] = g_wbar[g*64 + tid];
    for (int i = tid; i < 24*NC; i += SFT) {
        int hr = i / NC, n = i - hr*NC;
        int h = hr >> 2, r = hr & 3;
        s_a[hr*NC + n] = g_attn[((size_t)((b*H_ + h)*NQ + (r*G_ + g)))*NC + n];
    }
    __syncthreads();

    {
        const int half = tid & 1;
        const int l0 = half * 32;
#pragma unroll
        for (int nb = 0; nb < 2; nb++) {
            int n = (tid >> 1) + nb * 256;
            float mu = 0.f, qf = 0.f;
            if (n < NC) {
                const float* m = &s_mid[n*65];
#pragma unroll 8
                for (int l = l0; l < l0 + 32; l++) mu += m[l]*s_wb[l];
                for (int i2 = l0; i2 < l0 + 32; i2++) {
                    const float* Mi = &s_M[i2*64];
                    float t = 0.f;
#pragma unroll 16
                    for (int j = 0; j < 64; j++) t += Mi[j]*m[j];
                    qf += m[i2]*t;
                }
            }
            mu += __shfl_xor_sync(0xffffffffu, mu, 1);
            qf += __shfl_xor_sync(0xffffffffu, qf, 1);
            if (n < NC && half == 0) {
                float var = qf * (1.0f/(float)D_) - mu*mu;
                s_mu[n] = mu;
                s_rs[n] = rsqrtf(var + EPS);
            }
        }
    }
    __syncthreads();

    const size_t base = (size_t)(b*G_ + g) * 24;
    for (int idx = tid; idx < 24*66; idx += SFT) {
        int hr = idx / 66, j = idx - hr*66;
        const float* a = &s_a[hr*NC];
        float acc = 0.f;
        if (j < 64) {
            for (int n = 0; n < NC; n++) acc += a[n]*s_rs[n]*s_mid[n*65 + j];
            gc[(base + hr)*64 + j] = acc;
        } else if (j == 64) {
            for (int n = 0; n < NC; n++) acc += a[n]*s_rs[n]*s_mu[n];
            gs1[base + hr] = acc;
        } else {
            for (int n = 0; n < NC; n++) acc += a[n];
            gs0[base + hr] = acc;
        }
    }
}

// ---------------- combine: out = gv2*(c.W - s1) + bv2*s0 + skip -------------
__global__ void __launch_bounds__(256) combine_kernel(
    const float* __restrict__ Wconv, const float* __restrict__ gv2,
    const float* __restrict__ bv2, const float* __restrict__ gc,
    const float* __restrict__ gs1, const float* __restrict__ gs0,
    const float* __restrict__ skip,
    __nv_bfloat16* __restrict__ oph, __nv_bfloat16* __restrict__ opl) {
    __shared__ float sW[64*129];
    __shared__ float sc[16*64], ss1[16], ss0[16], sgv[128], sbv[128];
    const int g = blockIdx.x, h = blockIdx.y, tid = threadIdx.x;
    for (int i = tid; i < 8192; i += 256) {
        int l = i >> 7, dc = i & 127;
        sW[l*129 + dc] = Wconv[((size_t)(g*64 + l))*D_ + h*DH + dc];
    }
    for (int i = tid; i < 1024; i += 256) {
        int row = i >> 6, l = i & 63;
        int b = row >> 2, r = row & 3;
        sc[row*64 + l] = gc[(((size_t)(b*G_ + g))*24 + h*4 + r)*64 + l];
    }
    if (tid < 16) {
        int b = tid >> 2, r = tid & 3;
        ss1[tid] = gs1[((size_t)(b*G_ + g))*24 + h*4 + r];
        ss0[tid] = gs0[((size_t)(b*G_ + g))*24 + h*4 + r];
    }
    if (tid < 128) { sgv[tid] = gv2[h*DH + tid]; sbv[tid] = bv2[h*DH + tid]; }
    __syncthreads();
#pragma unroll
    for (int rep = 0; rep < 8; rep++) {
        int o = rep*256 + tid;
        int row = o >> 7, dc = o & 127;
        int b = row >> 2, r = row & 3;
        const float* c = &sc[row*64];
        float wd = 0.f;
#pragma unroll 16
        for (int l = 0; l < 64; l++) wd += c[l]*sW[l*129 + dc];
        float sk = skip[(((size_t)(b*H_ + h))*NQ + r*G_ + g)*DH + dc];
        float out = sgv[dc]*(wd - ss1[row]) + sbv[dc]*ss0[row] + sk;
        size_t oi = ((size_t)(b*NQ + r*G_ + g))*D_ + h*DH + dc;
        __nv_bfloat16 hv, lv;
        split2(out, hv, lv);
        oph[oi] = hv;
        opl[oi] = lv;
    }
}

// ---------------- launch ----------------------------------------------------
extern "C" void kernel_launch(void* const* d_in, const int* in_sizes, int n_in,
                              void* d_out, int out_size) {
    const float* x     = (const float*)d_in[0];
    const float* ctx   = (const float*)d_in[1];
    const float* Wq    = (const float*)d_in[2];
    const float* gq    = (const float*)d_in[3];
    const float* bq    = (const float*)d_in[4];
    const float* Wk    = (const float*)d_in[5];
    const float* gk    = (const float*)d_in[6];
    const float* bk    = (const float*)d_in[7];
    const float* Wv    = (const float*)d_in[8];
    const float* gv1   = (const float*)d_in[9];
    const float* bv1   = (const float*)d_in[10];
    const float* Wconv = (const float*)d_in[11];
    const float* gv2   = (const float*)d_in[12];
    const float* bv2   = (const float*)d_in[13];
    const float* Wo    = (const float*)d_in[14];
    const float* go    = (const float*)d_in[15];
    const float* bo    = (const float*)d_in[16];
    float* out = (float*)d_out;

    float *pq, *pk, *pmid, *psim, *pattn, *pskip, *pgc, *pgs1, *pgs0;
    cudaGetSymbolAddress((void**)&pq, g_q);
    cudaGetSymbolAddress((void**)&pk, g_k);
    cudaGetSymbolAddress((void**)&pmid, g_mid);
    cudaGetSymbolAddress((void**)&psim, g_sim);
    cudaGetSymbolAddress((void**)&pattn, g_attn);
    cudaGetSymbolAddress((void**)&pskip, g_skip);
    cudaGetSymbolAddress((void**)&pgc, g_c);
    cudaGetSymbolAddress((void**)&pgs1, g_s1);
    cudaGetSymbolAddress((void**)&pgs0, g_s0);
    __nv_bfloat16 *xh,*xl,*ch,*cl,*oph,*opl,*wqh,*wql,*wkh,*wkl,*woh,*wol,*wvh,*wvl;
    __nv_bfloat16 *qh,*ql,*kh,*kl,*cth,*ctl,*ath,*atl;
    cudaGetSymbolAddress((void**)&xh,  s_xh);  cudaGetSymbolAddress((void**)&xl,  s_xl);
    cudaGetSymbolAddress((void**)&ch,  s_ch);  cudaGetSymbolAddress((void**)&cl,  s_cl);
    cudaGetSymbolAddress((void**)&oph, s_oph); cudaGetSymbolAddress((void**)&opl, s_opl);
    cudaGetSymbolAddress((void**)&wqh, s_wqh); cudaGetSymbolAddress((void**)&wql, s_wql);
    cudaGetSymbolAddress((void**)&wkh, s_wkh); cudaGetSymbolAddress((void**)&wkl, s_wkl);
    cudaGetSymbolAddress((void**)&woh, s_woh); cudaGetSymbolAddress((void**)&wol, s_wol);
    cudaGetSymbolAddress((void**)&wvh, s_wvh); cudaGetSymbolAddress((void**)&wvl, s_wvl);
    cudaGetSymbolAddress((void**)&qh, s_qh2);  cudaGetSymbolAddress((void**)&ql, s_ql2);
    cudaGetSymbolAddress((void**)&kh, s_kh2);  cudaGetSymbolAddress((void**)&kl, s_kl2);
    cudaGetSymbolAddress((void**)&cth, s_cth); cudaGetSymbolAddress((void**)&ctl, s_ctl);
    cudaGetSymbolAddress((void**)&ath, s_ath); cudaGetSymbolAddress((void**)&atl, s_atl);

    cudaFuncSetAttribute(hmma_gemm,
                         cudaFuncAttributeMaxDynamicSharedMemorySize, HG_SMEM);
    cudaFuncSetAttribute(stageF1_kernel,
                         cudaFuncAttributeMaxDynamicSharedMemorySize, SF1_SMEM);
    cudaFuncSetAttribute(ln_rows,
                         cudaFuncAttributeMaxDynamicSharedMemorySize, GL*4);

    // 0 split ctx, 1 splitT Wv, 2 split x, 3 mid GEMM (profiled)
    split_kernel<<<(B_*NC*D_/4 + 255)/256, 256>>>(ctx, ch, cl, B_*NC*D_/4);
    splitT_kernel<<<dim3(GL/32, D_/64), 256>>>(Wv, wvh, wvl, D_, GL);
    split_kernel<<<(B_*NQ*D_/4 + 255)/256, 256>>>(x, xh, xl, B_*NQ*D_/4);
    hmma_gemm<<<dim3(GL/64, 17), 128, HG_SMEM>>>(ch, cl, wvh, wvl, pmid,
        D_, 17, B_*NC, GL, GL, 0, 0, 0);
    mid_stats_kernel<<<B_*NC, 256>>>(pmid);
    // q / k projections
    splitT_kernel<<<dim3(D_/32, D_/64), 256>>>(Wq, wqh, wql, D_, D_);
    hmma_gemm<<<dim3(D_/64, 26), 128, HG_SMEM>>>(xh, xl, wqh, wql, pq,
        D_, 26, B_*NQ, D_, D_, 0, 0, 0);
    ln_rows<<<B_*NQ, 256, D_*4>>>(pq, gq, bq, pq, D_);
    splitT_kernel<<<dim3(D_/32, D_/64), 256>>>(Wk, wkh, wkl, D_, D_);
    hmma_gemm<<<dim3(D_/64, 17), 128, HG_SMEM>>>(ch, cl, wkh, wkl, pk,
        D_, 17, B_*NC, D_, D_, 0, 0, 0);
    ln_rows<<<B_*NC, 256, D_*4>>>(pk, gk, bk, pk, D_);
    // attention: sim GEMM -> softmax -> skip GEMM
    split_head_q<<<(B_*NQ*D_/4 + 255)/256, 256>>>(pq, qh, ql);
    split_head_k<<<(BH*320*DH/4 + 255)/256, 256>>>(pk, kh, kl);
    hmma_gemm<<<dim3(5, BH*7), 128, HG_SMEM>>>(qh, ql, kh, kl, psim,
        DH, 7, NQ, NC, NC, (size_t)448*DH, (size_t)320*DH, (size_t)NQ*NC);
    softmax_kernel<<<dim3(13, BH), 256>>>(psim, pattn, ath, atl);
    split_ctxT<<<dim3(10, 4, BH), 256>>>(ctx, cth, ctl);
    hmma_gemm<<<dim3(2, BH*7), 128, HG_SMEM>>>(ath, atl, cth, ctl, pskip,
        320, 7, NQ, DH, DH, (size_t)448*320, (size_t)DH*320, (size_t)NQ*DH);
    // v-path analytic LN + combine
    prep_kernel<<<G_, 256>>>(Wconv);
    stageF1_kernel<<<dim3(G_, B_), SFT, SF1_SMEM>>>(gv1, bv1, pgc, pgs1, pgs0);
    combine_kernel<<<dim3(G_, H_), 256>>>(Wconv, gv2, bv2, pgc, pgs1, pgs0,
                                          pskip, oph, opl);
    // output projection + LN
    splitT_kernel<<<dim3(D_/32, D_/64), 256>>>(Wo, woh, wol, D_, D_);
    hmma_gemm<<<dim3(D_/64, 26), 128, HG_SMEM>>>(oph, opl, woh, wol, pq,
        D_, 26, B_*NQ, D_, D_, 0, 0, 0);
    ln_rows<<<B_*NQ, 256, D_*4>>>(pq, go, bo, out, D_);
}